// round 5
// baseline (speedup 1.0000x reference)
#include <cuda_runtime.h>
#include <cuda_fp16.h>
#include <cstdint>
#include <cstddef>

#define B_    64
#define N_    1024
#define DIN_  512
#define DH_   1024

#define BM 128
#define BN 128
#define BK 32
#define SSTRIDE 40   // fp16 elems per smem row: 32 data + 8 pad
#define TS 3
#define STAGE_HALFS (2 * BM * SSTRIDE)             // A tile + B tile per stage
#define GEMM_SMEM (TS * STAGE_HALFS * 2)           // bytes = 61440

// ------------------------- static device scratch -------------------------
__device__ __half g_Xh[(size_t)B_ * N_ * DIN_];
__device__ __half g_W1T[(size_t)DH_ * DIN_];
__device__ __half g_W2T[(size_t)DH_ * DH_];
__device__ __half g_H1[(size_t)B_ * N_ * DH_];
__device__ __half g_ET[(size_t)B_ * DH_ * N_];
__device__ float  g_agg[B_ * DH_];
__device__ float  g_T[B_ * DH_];
__device__ int    g_nv[B_];
__device__ int    g_kk[B_];
__device__ unsigned g_bits[B_ * (N_ / 32)];

// ------------------------- helpers -------------------------
__device__ __forceinline__ float keyToFloat16(unsigned k32) {
    unsigned t = k32 >> 16;
    unsigned short b = (t & 0x8000u) ? (unsigned short)(t ^ 0x8000u)
                                     : (unsigned short)(~t & 0xFFFFu);
    return __half2float(__ushort_as_half(b));
}

// fp16-out MMA (C=0), then promote to fp32 accumulators.
__device__ __forceinline__ void mma16816_h(float* c, const uint32_t* a, uint32_t b0, uint32_t b1) {
    uint32_t d0, d1;
    const uint32_t z = 0u;
    asm volatile(
        "mma.sync.aligned.m16n8k16.row.col.f16.f16.f16.f16 "
        "{%0,%1},{%2,%3,%4,%5},{%6,%7},{%8,%9};\n"
        : "=r"(d0), "=r"(d1)
        : "r"(a[0]), "r"(a[1]), "r"(a[2]), "r"(a[3]), "r"(b0), "r"(b1), "r"(z), "r"(z));
    float2 f0 = __half22float2(*reinterpret_cast<__half2*>(&d0));
    float2 f1 = __half22float2(*reinterpret_cast<__half2*>(&d1));
    c[0] += f0.x; c[1] += f0.y; c[2] += f1.x; c[3] += f1.y;
}
__device__ __forceinline__ void ldmat4(uint32_t* r, uint32_t addr) {
    asm volatile("ldmatrix.sync.aligned.m8n8.x4.shared.b16 {%0,%1,%2,%3},[%4];\n"
                 : "=r"(r[0]), "=r"(r[1]), "=r"(r[2]), "=r"(r[3])
                 : "r"(addr));
}
#define CP16(dst, src) asm volatile("cp.async.cg.shared.global [%0],[%1],16;\n" ::"r"(dst), "l"(src))

// 32x32 bit transpose (Hacker's Delight), involution.
template <int J>
__device__ __forceinline__ void tstep(unsigned* A, unsigned m) {
#pragma unroll
    for (int k0 = 0; k0 < 16; k0++) {
        int k = ((k0 & ~(J - 1)) << 1) | (k0 & (J - 1));
        unsigned t = (A[k] ^ (A[k + J] >> J)) & m;
        A[k] ^= t;
        A[k + J] ^= (t << J);
    }
}
__device__ __forceinline__ void transpose32(unsigned* A) {
    tstep<16>(A, 0x0000FFFFu);
    tstep<8>(A, 0x00FF00FFu);
    tstep<4>(A, 0x0F0F0F0Fu);
    tstep<2>(A, 0x33333333u);
    tstep<1>(A, 0x55555555u);
}
__device__ __forceinline__ unsigned radix_rank16(const unsigned* planes, int r) {
    unsigned C = 0xFFFFFFFFu, prefix = 0u;
#pragma unroll
    for (int bit = 31; bit >= 16; --bit) {
        unsigned P = planes[31 - bit];
        unsigned zeros = C & ~P;
        int c0 = __popc(zeros);
#pragma unroll
        for (int o = 16; o; o >>= 1) c0 += __shfl_xor_sync(0xFFFFFFFFu, c0, o);
        if (r < c0) {
            C = zeros;
        } else {
            r -= c0;
            C &= P;
            prefix |= (1u << bit);
        }
    }
    return prefix;
}

// ------------------------- prep kernels -------------------------
__global__ void castX_kernel(const float* __restrict__ X) {
    size_t i = (size_t)blockIdx.x * blockDim.x + threadIdx.x;
    float4 v = ((const float4*)X)[i];
    __half2* p = (__half2*)&g_Xh[4 * i];
    p[0] = __floats2half2_rn(v.x, v.y);
    p[1] = __floats2half2_rn(v.z, v.w);
}

__global__ void transW_kernel(const float* __restrict__ W, __half* __restrict__ WT, int Krows) {
    __shared__ float tile[32][33];
    int tx = threadIdx.x, ty = threadIdx.y;
    int x = blockIdx.x * 32 + tx;
#pragma unroll
    for (int i = 0; i < 32; i += 8) {
        int y = blockIdx.y * 32 + ty + i;
        tile[ty + i][tx] = W[(size_t)y * DH_ + x];
    }
    __syncthreads();
    int xo = blockIdx.y * 32 + tx;
#pragma unroll
    for (int i = 0; i < 32; i += 8) {
        int yo = blockIdx.x * 32 + ty + i;
        WT[(size_t)yo * Krows + xo] = __float2half_rn(tile[tx][ty + i]);
    }
}

__global__ void nvbits_kernel(const float* __restrict__ mask) {
    int b = blockIdx.x, t = threadIdx.x;
    int v = mask[(size_t)b * N_ + t] > 0.0f;
    unsigned word = __ballot_sync(0xFFFFFFFFu, v);
    __shared__ int cnt;
    if (t == 0) cnt = 0;
    __syncthreads();
    if ((t & 31) == 0) {
        g_bits[b * 32 + (t >> 5)] = word;
        atomicAdd(&cnt, __popc(word));
    }
    __syncthreads();
    if (t == 0) {
        g_nv[b] = cnt;
        g_kk[b] = (int)((float)cnt * 0.1f);
    }
}

// ------------------------- main GEMM (fp16 MMA, fp32 reg accum) ---------
// A [.., K] row-major; B [.., K] row-major (col-major MMA operand).
// out[r, c] (row stride N) = A[r,:]·B[c,:] + bias; RELU optional.
template <bool RELU, bool BIAS_BY_ROW>
__global__ void __launch_bounds__(256, 2) gemm_fp16(
    const __half* __restrict__ A, const __half* __restrict__ B,
    const float* __restrict__ bias, __half* __restrict__ out,
    int K, int N, size_t zA, size_t zB, size_t zC) {
    extern __shared__ __half sm[];

    A += (size_t)blockIdx.z * zA;
    B += (size_t)blockIdx.z * zB;
    out += (size_t)blockIdx.z * zC;

    int tid = threadIdx.x;
    int lane = tid & 31;
    int wid = tid >> 5;
    int wm = (wid >> 2) * 64;
    int wn = (wid & 3) * 32;
    int gq = lane >> 2, tg = lane & 3;
    int mBase = blockIdx.y * BM, nBase = blockIdx.x * BN;
    int KT = K / BK;

    float acc[4][4][4];
#pragma unroll
    for (int a = 0; a < 4; a++)
#pragma unroll
        for (int b = 0; b < 4; b++)
#pragma unroll
            for (int c = 0; c < 4; c++) acc[a][b][c] = 0.f;

    auto load = [&](int kt, int s) {
        __half* sa = sm + s * STAGE_HALFS;
        int k0 = kt * BK;
#pragma unroll
        for (int p = 0; p < 2; p++) {
            int v = tid + 256 * p;
            int row = v >> 2;
            int cv = (v & 3) * 8;
            uint32_t dA = (uint32_t)__cvta_generic_to_shared(sa + row * SSTRIDE + cv);
            CP16(dA, A + (size_t)(mBase + row) * K + k0 + cv);
            uint32_t dB = (uint32_t)__cvta_generic_to_shared(sa + BM * SSTRIDE + row * SSTRIDE + cv);
            CP16(dB, B + (size_t)(nBase + row) * K + k0 + cv);
        }
        asm volatile("cp.async.commit_group;\n");
    };

    load(0, 0);
    if (KT > 1) load(1, 1);
    for (int kt = 0; kt < KT; kt++) {
        int s = kt % TS;
        if (kt + 1 < KT) {
            asm volatile("cp.async.wait_group 1;\n");
        } else {
            asm volatile("cp.async.wait_group 0;\n");
        }
        __syncthreads();
        if (kt + 2 < KT) load(kt + 2, (kt + 2) % TS);

        const __half* sa = sm + s * STAGE_HALFS;
        const __half* sb = sa + BM * SSTRIDE;
#pragma unroll
        for (int kk = 0; kk < BK; kk += 16) {
            uint32_t af[4][4];
#pragma unroll
            for (int mi = 0; mi < 4; mi++) {
                uint32_t ad = (uint32_t)__cvta_generic_to_shared(
                    sa + (wm + mi * 16 + (lane & 15)) * SSTRIDE + kk + (lane >> 4) * 8);
                ldmat4(af[mi], ad);
            }
#pragma unroll
            for (int ni = 0; ni < 4; ni++) {
                const __half* bp = sb + (wn + ni * 8 + gq) * SSTRIDE + kk + 2 * tg;
                uint32_t b0 = *(const uint32_t*)bp;
                uint32_t b1v = *(const uint32_t*)(bp + 8);
#pragma unroll
                for (int mi = 0; mi < 4; mi++) mma16816_h(acc[mi][ni], af[mi], b0, b1v);
            }
        }
    }

#pragma unroll
    for (int mi = 0; mi < 4; mi++) {
        int r0 = mBase + wm + mi * 16 + gq;
        float bvR0 = 0.f, bvR1 = 0.f;
        if (BIAS_BY_ROW) { bvR0 = bias[r0]; bvR1 = bias[r0 + 8]; }
#pragma unroll
        for (int ni = 0; ni < 4; ni++) {
            int col = nBase + wn + ni * 8 + 2 * tg;
            float v00, v01, v10, v11;
            if (BIAS_BY_ROW) {
                v00 = acc[mi][ni][0] + bvR0; v01 = acc[mi][ni][1] + bvR0;
                v10 = acc[mi][ni][2] + bvR1; v11 = acc[mi][ni][3] + bvR1;
            } else {
                float bv0 = bias[col], bv1 = bias[col + 1];
                v00 = acc[mi][ni][0] + bv0; v01 = acc[mi][ni][1] + bv1;
                v10 = acc[mi][ni][2] + bv0; v11 = acc[mi][ni][3] + bv1;
            }
            if (RELU) {
                v00 = fmaxf(v00, 0.f); v01 = fmaxf(v01, 0.f);
                v10 = fmaxf(v10, 0.f); v11 = fmaxf(v11, 0.f);
            }
            *(__half2*)(out + (size_t)r0 * N + col) = __floats2half2_rn(v00, v01);
            *(__half2*)(out + (size_t)(r0 + 8) * N + col) = __floats2half2_rn(v10, v11);
        }
    }
}

// ------------------------- trimmed-mean select -------------------------
__global__ void __launch_bounds__(256) select_kernel() {
    int warp = (blockIdx.x << 3) + (threadIdx.x >> 5);
    int lane = threadIdx.x & 31;
    int b = warp >> 10;
    const __half* col = g_ET + ((size_t)warp << 10);

    unsigned keys[32];
#pragma unroll
    for (int j = 0; j < 4; j++) {
        int n0 = j * 256 + lane * 8;
        uint4 v = *(const uint4*)(col + n0);
        unsigned wbits = g_bits[(b << 5) + (n0 >> 5)];
        unsigned ws[4] = {v.x, v.y, v.z, v.w};
#pragma unroll
        for (int i = 0; i < 8; i++) {
            unsigned h = (ws[i >> 1] >> ((i & 1) * 16)) & 0xFFFFu;
            unsigned k16 = (h & 0x8000u) ? (~h & 0xFFFFu) : (h | 0x8000u);
            unsigned bit = (wbits >> ((n0 + i) & 31)) & 1u;
            keys[j * 8 + i] = bit ? (k16 << 16) : 0xFFFF0000u;
        }
    }

    int nv = g_nv[b], kT = g_kk[b];

    transpose32(keys);
    unsigned T2 = radix_rank16(keys, nv - kT - 1);
    unsigned T1 = 0;
    if (kT > 0) T1 = radix_rank16(keys, kT - 1);
    transpose32(keys);

    int c1 = 0, c2 = 0;
    float s1 = 0.f, s2 = 0.f;
#pragma unroll
    for (int i = 0; i < 32; i++) {
        unsigned kv = keys[i];
        float fv = keyToFloat16(kv);
        if (kT > 0 && kv < T1) { c1++; s1 += fv; }
        if (kv < T2) { c2++; s2 += fv; }
    }
#pragma unroll
    for (int o = 16; o; o >>= 1) {
        c1 += __shfl_xor_sync(0xFFFFFFFFu, c1, o);
        c2 += __shfl_xor_sync(0xFFFFFFFFu, c2, o);
        s1 += __shfl_xor_sync(0xFFFFFFFFu, s1, o);
        s2 += __shfl_xor_sync(0xFFFFFFFFu, s2, o);
    }
    float Sk = (kT > 0) ? (s1 + (float)(kT - c1) * keyToFloat16(T1)) : 0.f;
    float Snk = s2 + (float)((nv - kT) - c2) * keyToFloat16(T2);
    if (lane == 0) g_agg[warp] = (Snk - Sk) / (float)(nv - 2 * kT);
}

// ------------------------- decode MLP -------------------------
__global__ void decode1_kernel(const float* __restrict__ W3, const float* __restrict__ b3) {
    __shared__ float sa[8][1024];
    int h = blockIdx.x * 128 + threadIdx.x;
    int bg = blockIdx.y * 8;
    for (int i = threadIdx.x; i < 8 * 1024; i += 128)
        sa[i >> 10][i & 1023] = g_agg[(bg + (i >> 10)) * 1024 + (i & 1023)];
    __syncthreads();
    float accv[8];
#pragma unroll
    for (int ii = 0; ii < 8; ii++) accv[ii] = 0.f;
    for (int k2 = 0; k2 < 1024; k2++) {
        float w = W3[(size_t)k2 * 1024 + h];
#pragma unroll
        for (int ii = 0; ii < 8; ii++) accv[ii] += sa[ii][k2] * w;
    }
    float bb = b3[h];
#pragma unroll
    for (int ii = 0; ii < 8; ii++) g_T[(bg + ii) * 1024 + h] = fmaxf(accv[ii] + bb, 0.f);
}

__global__ void decode2_kernel(const float* __restrict__ W4, const float* __restrict__ b4,
                               float* __restrict__ out) {
    int gw = blockIdx.x * 8 + (threadIdx.x >> 5);
    int lane = threadIdx.x & 31;
    if (gw >= 640) return;
    int b = gw / 10, o = gw - 10 * b;
    float acc = 0.f;
#pragma unroll
    for (int i = 0; i < 32; i++) {
        int kidx = i * 32 + lane;
        acc += g_T[b * 1024 + kidx] * W4[(size_t)kidx * 10 + o];
    }
#pragma unroll
    for (int oo = 16; oo; oo >>= 1) acc += __shfl_xor_sync(0xFFFFFFFFu, acc, oo);
    if (lane == 0) out[b * 10 + o] = acc + b4[o];
}

// ------------------------- launch -------------------------
extern "C" void kernel_launch(void* const* d_in, const int* in_sizes, int n_in,
                              void* d_out, int out_size) {
    const float* X = (const float*)d_in[0];
    const float* mask = (const float*)d_in[1];
    const float* W1 = (const float*)d_in[2];
    const float* b1 = (const float*)d_in[3];
    const float* W2 = (const float*)d_in[4];
    const float* b2 = (const float*)d_in[5];
    const float* W3 = (const float*)d_in[6];
    const float* b3 = (const float*)d_in[7];
    const float* W4 = (const float*)d_in[8];
    const float* b4 = (const float*)d_in[9];
    float* out = (float*)d_out;

    void *pXh, *pW1T, *pW2T, *pH1, *pET;
    cudaGetSymbolAddress(&pXh, g_Xh);
    cudaGetSymbolAddress(&pW1T, g_W1T);
    cudaGetSymbolAddress(&pW2T, g_W2T);
    cudaGetSymbolAddress(&pH1, g_H1);
    cudaGetSymbolAddress(&pET, g_ET);

    cudaFuncSetAttribute(gemm_fp16<true, false>, cudaFuncAttributeMaxDynamicSharedMemorySize, GEMM_SMEM);
    cudaFuncSetAttribute(gemm_fp16<false, true>, cudaFuncAttributeMaxDynamicSharedMemorySize, GEMM_SMEM);

    castX_kernel<<<32768, 256>>>(X);
    transW_kernel<<<dim3(32, 16), dim3(32, 8)>>>(W1, (__half*)pW1T, DIN_);
    transW_kernel<<<dim3(32, 32), dim3(32, 8)>>>(W2, (__half*)pW2T, DH_);
    nvbits_kernel<<<64, 1024>>>(mask);

    // GEMM1: H1[m,h] = relu(X[m,:]·W1T[h,:] + b1[h])
    gemm_fp16<true, false><<<dim3(DH_ / BN, (B_ * N_) / BM, 1), 256, GEMM_SMEM>>>(
        (const __half*)pXh, (const __half*)pW1T, b1, (__half*)pH1,
        DIN_, DH_, 0, 0, 0);

    // GEMM2 (transposed out): ET[b][h][n] = W2T[h,:]·H1[b][n,:] + b2[h]
    gemm_fp16<false, true><<<dim3(N_ / BN, DH_ / 128, B_), 256, GEMM_SMEM>>>(
        (const __half*)pW2T, (const __half*)pH1, b2, (__half*)pET,
        DH_, N_, 0, (size_t)N_ * DH_, (size_t)DH_ * N_);

    select_kernel<<<(B_ * DH_) / 8, 256>>>();
    decode1_kernel<<<dim3(8, 8), 128>>>(W3, b3);
    decode2_kernel<<<80, 256>>>(W4, b4, out);
}

// round 6
// speedup vs baseline: 1.1502x; 1.1502x over previous
#include <cuda_runtime.h>
#include <cuda_fp16.h>
#include <cstdint>
#include <cstddef>

#define B_    64
#define N_    1024
#define DIN_  512
#define DH_   1024

#define BM 256               // block tile M
#define BN 128               // block tile N
#define BK 32
#define SSTRIDE 40           // fp16 elems per smem row: 32 data + 8 pad
#define TS 3
#define STAGE_HALFS ((BM + BN) * SSTRIDE)      // 15360 halfs per stage
#define GEMM_SMEM (TS * STAGE_HALFS * 2)       // 92160 bytes

// ------------------------- static device scratch -------------------------
__device__ __half g_Xh[(size_t)B_ * N_ * DIN_];
__device__ __half g_W1T[(size_t)DH_ * DIN_];
__device__ __half g_W2T[(size_t)DH_ * DH_];
__device__ __half g_H1[(size_t)B_ * N_ * DH_];
__device__ __half g_ET[(size_t)B_ * DH_ * N_];
__device__ float  g_agg[B_ * DH_];
__device__ float  g_T[B_ * DH_];
__device__ int    g_nv[B_];
__device__ int    g_kk[B_];
__device__ unsigned g_bits[B_ * (N_ / 32)];

// ------------------------- helpers -------------------------
__device__ __forceinline__ float keyToFloat16(unsigned k32) {
    unsigned t = k32 >> 16;
    unsigned short b = (t & 0x8000u) ? (unsigned short)(t ^ 0x8000u)
                                     : (unsigned short)(~t & 0xFFFFu);
    return __half2float(__ushort_as_half(b));
}

__device__ __forceinline__ void mma16816(float* c, const uint32_t* a, uint32_t b0, uint32_t b1) {
    asm volatile(
        "mma.sync.aligned.m16n8k16.row.col.f32.f16.f16.f32 "
        "{%0,%1,%2,%3},{%4,%5,%6,%7},{%8,%9},{%0,%1,%2,%3};\n"
        : "+f"(c[0]), "+f"(c[1]), "+f"(c[2]), "+f"(c[3])
        : "r"(a[0]), "r"(a[1]), "r"(a[2]), "r"(a[3]), "r"(b0), "r"(b1));
}
__device__ __forceinline__ void ldmat4(uint32_t* r, uint32_t addr) {
    asm volatile("ldmatrix.sync.aligned.m8n8.x4.shared.b16 {%0,%1,%2,%3},[%4];\n"
                 : "=r"(r[0]), "=r"(r[1]), "=r"(r[2]), "=r"(r[3])
                 : "r"(addr));
}
#define CP16(dst, src) asm volatile("cp.async.cg.shared.global [%0],[%1],16;\n" ::"r"(dst), "l"(src))

// 32x32 bit transpose (Hacker's Delight), involution.
template <int J>
__device__ __forceinline__ void tstep(unsigned* A, unsigned m) {
#pragma unroll
    for (int k0 = 0; k0 < 16; k0++) {
        int k = ((k0 & ~(J - 1)) << 1) | (k0 & (J - 1));
        unsigned t = (A[k] ^ (A[k + J] >> J)) & m;
        A[k] ^= t;
        A[k + J] ^= (t << J);
    }
}
__device__ __forceinline__ void transpose32(unsigned* A) {
    tstep<16>(A, 0x0000FFFFu);
    tstep<8>(A, 0x00FF00FFu);
    tstep<4>(A, 0x0F0F0F0Fu);
    tstep<2>(A, 0x33333333u);
    tstep<1>(A, 0x55555555u);
}
__device__ __forceinline__ unsigned radix_rank16(const unsigned* planes, int r) {
    unsigned C = 0xFFFFFFFFu, prefix = 0u;
#pragma unroll
    for (int bit = 31; bit >= 16; --bit) {
        unsigned P = planes[31 - bit];
        unsigned zeros = C & ~P;
        int c0 = __popc(zeros);
#pragma unroll
        for (int o = 16; o; o >>= 1) c0 += __shfl_xor_sync(0xFFFFFFFFu, c0, o);
        if (r < c0) {
            C = zeros;
        } else {
            r -= c0;
            C &= P;
            prefix |= (1u << bit);
        }
    }
    return prefix;
}

// ------------------------- prep kernels -------------------------
__global__ void castX_kernel(const float* __restrict__ X) {
    size_t i = (size_t)blockIdx.x * blockDim.x + threadIdx.x;
    float4 v = ((const float4*)X)[i];
    __half2* p = (__half2*)&g_Xh[4 * i];
    p[0] = __floats2half2_rn(v.x, v.y);
    p[1] = __floats2half2_rn(v.z, v.w);
}

__global__ void transW_kernel(const float* __restrict__ W, __half* __restrict__ WT, int Krows) {
    __shared__ float tile[32][33];
    int tx = threadIdx.x, ty = threadIdx.y;
    int x = blockIdx.x * 32 + tx;
#pragma unroll
    for (int i = 0; i < 32; i += 8) {
        int y = blockIdx.y * 32 + ty + i;
        tile[ty + i][tx] = W[(size_t)y * DH_ + x];
    }
    __syncthreads();
    int xo = blockIdx.y * 32 + tx;
#pragma unroll
    for (int i = 0; i < 32; i += 8) {
        int yo = blockIdx.x * 32 + ty + i;
        WT[(size_t)yo * Krows + xo] = __float2half_rn(tile[tx][ty + i]);
    }
}

__global__ void nvbits_kernel(const float* __restrict__ mask) {
    int b = blockIdx.x, t = threadIdx.x;
    int v = mask[(size_t)b * N_ + t] > 0.0f;
    unsigned word = __ballot_sync(0xFFFFFFFFu, v);
    __shared__ int cnt;
    if (t == 0) cnt = 0;
    __syncthreads();
    if ((t & 31) == 0) {
        g_bits[b * 32 + (t >> 5)] = word;
        atomicAdd(&cnt, __popc(word));
    }
    __syncthreads();
    if (t == 0) {
        g_nv[b] = cnt;
        g_kk[b] = (int)((float)cnt * 0.1f);
    }
}

// ------------------------- main GEMM (fp16 MMA, fp32 accum) -------------
// A [.., K] row-major; B [.., K] row-major (col-major MMA operand).
// Block tile 256x128; 8 warps, each 64x64 (4 m-tiles x 8 n-tiles).
// out[r, c] (row stride N) = A[r,:]·B[c,:] + bias; RELU optional.
template <bool RELU, bool BIAS_BY_ROW>
__global__ void __launch_bounds__(256, 1) gemm_fp16(
    const __half* __restrict__ A, const __half* __restrict__ B,
    const float* __restrict__ bias, __half* __restrict__ out,
    int K, int N, size_t zB, size_t zC) {
    extern __shared__ __half sm[];

    B += (size_t)blockIdx.z * zB;
    out += (size_t)blockIdx.z * zC;

    const int tid = threadIdx.x;
    const int lane = tid & 31;
    const int wid = tid >> 5;
    const int wm = (wid >> 1) * 64;
    const int wn = (wid & 1) * 64;
    const int gq = lane >> 2, tg = lane & 3;
    const int mBase = blockIdx.y * BM, nBase = blockIdx.x * BN;
    const int KT = K / BK;

    float acc[4][8][4];
#pragma unroll
    for (int a = 0; a < 4; a++)
#pragma unroll
        for (int b = 0; b < 8; b++)
#pragma unroll
            for (int c = 0; c < 4; c++) acc[a][b][c] = 0.f;

    auto load = [&](int kt, int s) {
        __half* sa = sm + s * STAGE_HALFS;
        int k0 = kt * BK;
#pragma unroll
        for (int p = 0; p < 6; p++) {
            int v = tid + 256 * p;  // 0..1535 -> 384 rows x 4 x 16B
            int row = v >> 2;
            int cv = (v & 3) * 8;
            uint32_t d = (uint32_t)__cvta_generic_to_shared(sa + row * SSTRIDE + cv);
            const __half* src = (row < BM) ? (A + (size_t)(mBase + row) * K + k0 + cv)
                                           : (B + (size_t)(nBase + row - BM) * K + k0 + cv);
            CP16(d, src);
        }
        asm volatile("cp.async.commit_group;\n");
    };

    load(0, 0);
    if (KT > 1) load(1, 1);
    for (int kt = 0; kt < KT; kt++) {
        int s = kt % TS;
        if (kt + 1 < KT) {
            asm volatile("cp.async.wait_group 1;\n");
        } else {
            asm volatile("cp.async.wait_group 0;\n");
        }
        __syncthreads();
        if (kt + 2 < KT) load(kt + 2, (kt + 2) % TS);

        const __half* sa = sm + s * STAGE_HALFS;
        const __half* sb = sa + BM * SSTRIDE;
#pragma unroll
        for (int kk = 0; kk < BK; kk += 16) {
            uint32_t af[4][4];
#pragma unroll
            for (int mi = 0; mi < 4; mi++) {
                uint32_t ad = (uint32_t)__cvta_generic_to_shared(
                    sa + (wm + mi * 16 + (lane & 15)) * SSTRIDE + kk + (lane >> 4) * 8);
                ldmat4(af[mi], ad);
            }
            uint32_t bf[4][4];
#pragma unroll
            for (int bj = 0; bj < 4; bj++) {
                int brow = wn + (2 * bj + ((lane >> 4) & 1)) * 8 + (lane & 7);
                int bcol = kk + ((lane >> 3) & 1) * 8;
                uint32_t bd = (uint32_t)__cvta_generic_to_shared(sb + brow * SSTRIDE + bcol);
                ldmat4(bf[bj], bd);
            }
#pragma unroll
            for (int mi = 0; mi < 4; mi++)
#pragma unroll
                for (int ni = 0; ni < 8; ni++) {
                    int bj = ni >> 1;
                    uint32_t b0 = bf[bj][(ni & 1) * 2];
                    uint32_t b1 = bf[bj][(ni & 1) * 2 + 1];
                    mma16816(acc[mi][ni], af[mi], b0, b1);
                }
        }
    }

#pragma unroll
    for (int mi = 0; mi < 4; mi++) {
        int r0 = mBase + wm + mi * 16 + gq;
        float bvR0 = 0.f, bvR1 = 0.f;
        if (BIAS_BY_ROW) { bvR0 = bias[r0]; bvR1 = bias[r0 + 8]; }
#pragma unroll
        for (int ni = 0; ni < 8; ni++) {
            int col = nBase + wn + ni * 8 + 2 * tg;
            float v00, v01, v10, v11;
            if (BIAS_BY_ROW) {
                v00 = acc[mi][ni][0] + bvR0; v01 = acc[mi][ni][1] + bvR0;
                v10 = acc[mi][ni][2] + bvR1; v11 = acc[mi][ni][3] + bvR1;
            } else {
                float bv0 = bias[col], bv1 = bias[col + 1];
                v00 = acc[mi][ni][0] + bv0; v01 = acc[mi][ni][1] + bv1;
                v10 = acc[mi][ni][2] + bv0; v11 = acc[mi][ni][3] + bv1;
            }
            if (RELU) {
                v00 = fmaxf(v00, 0.f); v01 = fmaxf(v01, 0.f);
                v10 = fmaxf(v10, 0.f); v11 = fmaxf(v11, 0.f);
            }
            *(__half2*)(out + (size_t)r0 * N + col) = __floats2half2_rn(v00, v01);
            *(__half2*)(out + (size_t)(r0 + 8) * N + col) = __floats2half2_rn(v10, v11);
        }
    }
}

// ------------------------- trimmed-mean select -------------------------
__global__ void __launch_bounds__(256) select_kernel() {
    int warp = (blockIdx.x << 3) + (threadIdx.x >> 5);
    int lane = threadIdx.x & 31;
    int b = warp >> 10;
    const __half* col = g_ET + ((size_t)warp << 10);

    unsigned keys[32];
#pragma unroll
    for (int j = 0; j < 4; j++) {
        int n0 = j * 256 + lane * 8;
        uint4 v = *(const uint4*)(col + n0);
        unsigned wbits = g_bits[(b << 5) + (n0 >> 5)];
        unsigned ws[4] = {v.x, v.y, v.z, v.w};
#pragma unroll
        for (int i = 0; i < 8; i++) {
            unsigned h = (ws[i >> 1] >> ((i & 1) * 16)) & 0xFFFFu;
            unsigned k16 = (h & 0x8000u) ? (~h & 0xFFFFu) : (h | 0x8000u);
            unsigned bit = (wbits >> ((n0 + i) & 31)) & 1u;
            keys[j * 8 + i] = bit ? (k16 << 16) : 0xFFFF0000u;
        }
    }

    int nv = g_nv[b], kT = g_kk[b];

    transpose32(keys);
    unsigned T2 = radix_rank16(keys, nv - kT - 1);
    unsigned T1 = 0;
    if (kT > 0) T1 = radix_rank16(keys, kT - 1);
    transpose32(keys);

    int c1 = 0, c2 = 0;
    float s1 = 0.f, s2 = 0.f;
#pragma unroll
    for (int i = 0; i < 32; i++) {
        unsigned kv = keys[i];
        float fv = keyToFloat16(kv);
        if (kT > 0 && kv < T1) { c1++; s1 += fv; }
        if (kv < T2) { c2++; s2 += fv; }
    }
#pragma unroll
    for (int o = 16; o; o >>= 1) {
        c1 += __shfl_xor_sync(0xFFFFFFFFu, c1, o);
        c2 += __shfl_xor_sync(0xFFFFFFFFu, c2, o);
        s1 += __shfl_xor_sync(0xFFFFFFFFu, s1, o);
        s2 += __shfl_xor_sync(0xFFFFFFFFu, s2, o);
    }
    float Sk = (kT > 0) ? (s1 + (float)(kT - c1) * keyToFloat16(T1)) : 0.f;
    float Snk = s2 + (float)((nv - kT) - c2) * keyToFloat16(T2);
    if (lane == 0) g_agg[warp] = (Snk - Sk) / (float)(nv - 2 * kT);
}

// ------------------------- decode MLP -------------------------
__global__ void decode1_kernel(const float* __restrict__ W3, const float* __restrict__ b3) {
    __shared__ float sa[8][1024];
    int h = blockIdx.x * 128 + threadIdx.x;
    int bg = blockIdx.y * 8;
    for (int i = threadIdx.x; i < 8 * 1024; i += 128)
        sa[i >> 10][i & 1023] = g_agg[(bg + (i >> 10)) * 1024 + (i & 1023)];
    __syncthreads();
    float accv[8];
#pragma unroll
    for (int ii = 0; ii < 8; ii++) accv[ii] = 0.f;
    for (int k2 = 0; k2 < 1024; k2++) {
        float w = W3[(size_t)k2 * 1024 + h];
#pragma unroll
        for (int ii = 0; ii < 8; ii++) accv[ii] += sa[ii][k2] * w;
    }
    float bb = b3[h];
#pragma unroll
    for (int ii = 0; ii < 8; ii++) g_T[(bg + ii) * 1024 + h] = fmaxf(accv[ii] + bb, 0.f);
}

__global__ void decode2_kernel(const float* __restrict__ W4, const float* __restrict__ b4,
                               float* __restrict__ out) {
    int gw = blockIdx.x * 8 + (threadIdx.x >> 5);
    int lane = threadIdx.x & 31;
    if (gw >= 640) return;
    int b = gw / 10, o = gw - 10 * b;
    float acc = 0.f;
#pragma unroll
    for (int i = 0; i < 32; i++) {
        int kidx = i * 32 + lane;
        acc += g_T[b * 1024 + kidx] * W4[(size_t)kidx * 10 + o];
    }
#pragma unroll
    for (int oo = 16; oo; oo >>= 1) acc += __shfl_xor_sync(0xFFFFFFFFu, acc, oo);
    if (lane == 0) out[b * 10 + o] = acc + b4[o];
}

// ------------------------- launch -------------------------
extern "C" void kernel_launch(void* const* d_in, const int* in_sizes, int n_in,
                              void* d_out, int out_size) {
    const float* X = (const float*)d_in[0];
    const float* mask = (const float*)d_in[1];
    const float* W1 = (const float*)d_in[2];
    const float* b1 = (const float*)d_in[3];
    const float* W2 = (const float*)d_in[4];
    const float* b2 = (const float*)d_in[5];
    const float* W3 = (const float*)d_in[6];
    const float* b3 = (const float*)d_in[7];
    const float* W4 = (const float*)d_in[8];
    const float* b4 = (const float*)d_in[9];
    float* out = (float*)d_out;

    void *pXh, *pW1T, *pW2T, *pH1, *pET;
    cudaGetSymbolAddress(&pXh, g_Xh);
    cudaGetSymbolAddress(&pW1T, g_W1T);
    cudaGetSymbolAddress(&pW2T, g_W2T);
    cudaGetSymbolAddress(&pH1, g_H1);
    cudaGetSymbolAddress(&pET, g_ET);

    cudaFuncSetAttribute(gemm_fp16<true, false>, cudaFuncAttributeMaxDynamicSharedMemorySize, GEMM_SMEM);
    cudaFuncSetAttribute(gemm_fp16<false, true>, cudaFuncAttributeMaxDynamicSharedMemorySize, GEMM_SMEM);

    castX_kernel<<<32768, 256>>>(X);
    transW_kernel<<<dim3(32, 16), dim3(32, 8)>>>(W1, (__half*)pW1T, DIN_);
    transW_kernel<<<dim3(32, 32), dim3(32, 8)>>>(W2, (__half*)pW2T, DH_);
    nvbits_kernel<<<64, 1024>>>(mask);

    // GEMM1: H1[m,h] = relu(X[m,:]·W1T[h,:] + b1[h])
    gemm_fp16<true, false><<<dim3(DH_ / BN, (B_ * N_) / BM, 1), 256, GEMM_SMEM>>>(
        (const __half*)pXh, (const __half*)pW1T, b1, (__half*)pH1,
        DIN_, DH_, 0, 0);

    // GEMM2 (transposed out): ET[b][h][n] = W2T[h,:]·H1[b][n,:] + b2[h]
    gemm_fp16<false, true><<<dim3(N_ / BN, DH_ / BM, B_), 256, GEMM_SMEM>>>(
        (const __half*)pW2T, (const __half*)pH1, b2, (__half*)pET,
        DH_, N_, (size_t)N_ * DH_, (size_t)DH_ * N_);

    select_kernel<<<(B_ * DH_) / 8, 256>>>();
    decode1_kernel<<<dim3(8, 8), 128>>>(W3, b3);
    decode2_kernel<<<80, 256>>>(W4, b4, out);
}

// round 7
// speedup vs baseline: 1.3910x; 1.2093x over previous
#include <cuda_runtime.h>
#include <cuda_fp16.h>
#include <cstdint>
#include <cstddef>

#define B_    64
#define N_    1024
#define DIN_  512
#define DH_   1024

#define BM 128
#define BN 128
#define BK 64
#define SSTRIDE 72           // fp16 elems per smem row: 64 data + 8 pad (144B)
#define TS 3
#define STAGE_HALFS ((BM + BN) * SSTRIDE)   // 18432 halfs = 36864 B
#define GEMM_SMEM (TS * STAGE_HALFS * 2)    // 110592 B

// ------------------------- static device scratch -------------------------
__device__ __half g_Xh[(size_t)B_ * N_ * DIN_];
__device__ __half g_W1T[(size_t)DH_ * DIN_];
__device__ __half g_W2T[(size_t)DH_ * DH_];
__device__ __half g_H1[(size_t)B_ * N_ * DH_];
__device__ __half g_ET[(size_t)B_ * DH_ * N_];
__device__ float  g_agg[B_ * DH_];
__device__ float  g_T[B_ * DH_];
__device__ int    g_nv[B_];
__device__ int    g_kk[B_];
__device__ unsigned g_bits[B_ * (N_ / 32)];

// ------------------------- helpers -------------------------
__device__ __forceinline__ float keyToFloat16(unsigned k32) {
    unsigned t = k32 >> 16;
    unsigned short b = (t & 0x8000u) ? (unsigned short)(t ^ 0x8000u)
                                     : (unsigned short)(~t & 0xFFFFu);
    return __half2float(__ushort_as_half(b));
}

__device__ __forceinline__ void mma16816(float* c, const uint32_t* a, uint32_t b0, uint32_t b1) {
    asm volatile(
        "mma.sync.aligned.m16n8k16.row.col.f32.f16.f16.f32 "
        "{%0,%1,%2,%3},{%4,%5,%6,%7},{%8,%9},{%0,%1,%2,%3};\n"
        : "+f"(c[0]), "+f"(c[1]), "+f"(c[2]), "+f"(c[3])
        : "r"(a[0]), "r"(a[1]), "r"(a[2]), "r"(a[3]), "r"(b0), "r"(b1));
}
__device__ __forceinline__ void ldmat4(uint32_t* r, uint32_t addr) {
    asm volatile("ldmatrix.sync.aligned.m8n8.x4.shared.b16 {%0,%1,%2,%3},[%4];\n"
                 : "=r"(r[0]), "=r"(r[1]), "=r"(r[2]), "=r"(r[3])
                 : "r"(addr));
}
#define CP16(dst, src) asm volatile("cp.async.cg.shared.global [%0],[%1],16;\n" ::"r"(dst), "l"(src))

// 32x32 bit transpose (Hacker's Delight), involution.
template <int J>
__device__ __forceinline__ void tstep(unsigned* A, unsigned m) {
#pragma unroll
    for (int k0 = 0; k0 < 16; k0++) {
        int k = ((k0 & ~(J - 1)) << 1) | (k0 & (J - 1));
        unsigned t = (A[k] ^ (A[k + J] >> J)) & m;
        A[k] ^= t;
        A[k + J] ^= (t << J);
    }
}
__device__ __forceinline__ void transpose32(unsigned* A) {
    tstep<16>(A, 0x0000FFFFu);
    tstep<8>(A, 0x00FF00FFu);
    tstep<4>(A, 0x0F0F0F0Fu);
    tstep<2>(A, 0x33333333u);
    tstep<1>(A, 0x55555555u);
}
// planes = bit-transposed keys (bits 31..16). Rank r over the warp's 1024 keys.
__device__ __forceinline__ unsigned radix_rank16(const unsigned* planes, int r) {
    unsigned C = 0xFFFFFFFFu, prefix = 0u;
#pragma unroll
    for (int bit = 31; bit >= 16; --bit) {
        unsigned P = planes[31 - bit];
        unsigned zeros = C & ~P;
        int c0 = __reduce_add_sync(0xFFFFFFFFu, __popc(zeros));
        if (r < c0) {
            C = zeros;
        } else {
            r -= c0;
            C &= P;
            prefix |= (1u << bit);
        }
    }
    return prefix;
}

// ------------------------- prep kernels -------------------------
__global__ void castX_kernel(const float* __restrict__ X) {
    size_t i = (size_t)blockIdx.x * blockDim.x + threadIdx.x;
    float4 v = ((const float4*)X)[i];
    __half2* p = (__half2*)&g_Xh[4 * i];
    p[0] = __floats2half2_rn(v.x, v.y);
    p[1] = __floats2half2_rn(v.z, v.w);
}

__global__ void transW_kernel(const float* __restrict__ W, __half* __restrict__ WT, int Krows) {
    __shared__ float tile[32][33];
    int tx = threadIdx.x, ty = threadIdx.y;
    int x = blockIdx.x * 32 + tx;
#pragma unroll
    for (int i = 0; i < 32; i += 8) {
        int y = blockIdx.y * 32 + ty + i;
        tile[ty + i][tx] = W[(size_t)y * DH_ + x];
    }
    __syncthreads();
    int xo = blockIdx.y * 32 + tx;
#pragma unroll
    for (int i = 0; i < 32; i += 8) {
        int yo = blockIdx.x * 32 + ty + i;
        WT[(size_t)yo * Krows + xo] = __float2half_rn(tile[tx][ty + i]);
    }
}

__global__ void nvbits_kernel(const float* __restrict__ mask) {
    int b = blockIdx.x, t = threadIdx.x;
    int v = mask[(size_t)b * N_ + t] > 0.0f;
    unsigned word = __ballot_sync(0xFFFFFFFFu, v);
    __shared__ int cnt;
    if (t == 0) cnt = 0;
    __syncthreads();
    if ((t & 31) == 0) {
        g_bits[b * 32 + (t >> 5)] = word;
        atomicAdd(&cnt, __popc(word));
    }
    __syncthreads();
    if (t == 0) {
        g_nv[b] = cnt;
        g_kk[b] = (int)((float)cnt * 0.1f);
    }
}

// ------------------------- main GEMM (fp16 MMA, fp32 accum) -------------
// A [.., K] row-major; B [.., K] row-major (col-major MMA operand).
// Block 128x128, 8 warps of 64x32, BK=64, 3-stage cp.async pipeline.
template <bool RELU, bool BIAS_BY_ROW>
__global__ void __launch_bounds__(256, 2) gemm_fp16(
    const __half* __restrict__ A, const __half* __restrict__ B,
    const float* __restrict__ bias, __half* __restrict__ out,
    int K, int N, size_t zB, size_t zC) {
    extern __shared__ __half sm[];

    B += (size_t)blockIdx.z * zB;
    out += (size_t)blockIdx.z * zC;

    const int tid = threadIdx.x;
    const int lane = tid & 31;
    const int wid = tid >> 5;
    const int wm = (wid >> 2) * 64;
    const int wn = (wid & 3) * 32;
    const int gq = lane >> 2, tg = lane & 3;
    const int mBase = blockIdx.y * BM, nBase = blockIdx.x * BN;
    const int KT = K / BK;

    float acc[4][4][4];
#pragma unroll
    for (int a = 0; a < 4; a++)
#pragma unroll
        for (int b = 0; b < 4; b++)
#pragma unroll
            for (int c = 0; c < 4; c++) acc[a][b][c] = 0.f;

    // stage layout: rows 0..127 = A tile, rows 128..255 = B tile, SSTRIDE halfs/row
    auto load = [&](int kt, int s) {
        __half* sa = sm + s * STAGE_HALFS;
        int k0 = kt * BK;
#pragma unroll
        for (int p = 0; p < 8; p++) {
            int v = tid + 256 * p;      // 0..2047 -> 256 rows x 8 chunks of 16B
            int row = v >> 3;
            int cv = (v & 7) * 8;
            uint32_t d = (uint32_t)__cvta_generic_to_shared(sa + row * SSTRIDE + cv);
            const __half* src = (row < BM) ? (A + (size_t)(mBase + row) * K + k0 + cv)
                                           : (B + (size_t)(nBase + row - BM) * K + k0 + cv);
            CP16(d, src);
        }
        asm volatile("cp.async.commit_group;\n");
    };

    load(0, 0);
    if (KT > 1) load(1, 1);
    for (int kt = 0; kt < KT; kt++) {
        int s = kt % TS;
        if (kt + 1 < KT) {
            asm volatile("cp.async.wait_group 1;\n");
        } else {
            asm volatile("cp.async.wait_group 0;\n");
        }
        __syncthreads();
        if (kt + 2 < KT) load(kt + 2, (kt + 2) % TS);

        const __half* sa = sm + s * STAGE_HALFS;
        const __half* sb = sa + BM * SSTRIDE;
#pragma unroll
        for (int kk = 0; kk < BK; kk += 16) {
            uint32_t af[4][4];
#pragma unroll
            for (int mi = 0; mi < 4; mi++) {
                uint32_t ad = (uint32_t)__cvta_generic_to_shared(
                    sa + (wm + mi * 16 + (lane & 15)) * SSTRIDE + kk + (lane >> 4) * 8);
                ldmat4(af[mi], ad);
            }
#pragma unroll
            for (int ni = 0; ni < 4; ni++) {
                const __half* bp = sb + (wn + ni * 8 + gq) * SSTRIDE + kk + 2 * tg;
                uint32_t b0 = *(const uint32_t*)bp;
                uint32_t b1v = *(const uint32_t*)(bp + 8);
#pragma unroll
                for (int mi = 0; mi < 4; mi++) mma16816(acc[mi][ni], af[mi], b0, b1v);
            }
        }
    }

#pragma unroll
    for (int mi = 0; mi < 4; mi++) {
        int r0 = mBase + wm + mi * 16 + gq;
        float bvR0 = 0.f, bvR1 = 0.f;
        if (BIAS_BY_ROW) { bvR0 = bias[r0]; bvR1 = bias[r0 + 8]; }
#pragma unroll
        for (int ni = 0; ni < 4; ni++) {
            int col = nBase + wn + ni * 8 + 2 * tg;
            float v00, v01, v10, v11;
            if (BIAS_BY_ROW) {
                v00 = acc[mi][ni][0] + bvR0; v01 = acc[mi][ni][1] + bvR0;
                v10 = acc[mi][ni][2] + bvR1; v11 = acc[mi][ni][3] + bvR1;
            } else {
                float bv0 = bias[col], bv1 = bias[col + 1];
                v00 = acc[mi][ni][0] + bv0; v01 = acc[mi][ni][1] + bv1;
                v10 = acc[mi][ni][2] + bv0; v11 = acc[mi][ni][3] + bv1;
            }
            if (RELU) {
                v00 = fmaxf(v00, 0.f); v01 = fmaxf(v01, 0.f);
                v10 = fmaxf(v10, 0.f); v11 = fmaxf(v11, 0.f);
            }
            *(__half2*)(out + (size_t)r0 * N + col) = __floats2half2_rn(v00, v01);
            *(__half2*)(out + (size_t)(r0 + 8) * N + col) = __floats2half2_rn(v10, v11);
        }
    }
}

// ------------------------- trimmed-mean select -------------------------
__global__ void __launch_bounds__(256) select_kernel() {
    int warp = (blockIdx.x << 3) + (threadIdx.x >> 5);  // b*1024 + h
    int lane = threadIdx.x & 31;
    int b = warp >> 10;
    const __half* col = g_ET + ((size_t)warp << 10);

    unsigned keys[32], planes[32];
#pragma unroll
    for (int j = 0; j < 4; j++) {
        int n0 = j * 256 + lane * 8;
        uint4 v = *(const uint4*)(col + n0);
        unsigned wbits = g_bits[(b << 5) + (n0 >> 5)];
        unsigned ws[4] = {v.x, v.y, v.z, v.w};
#pragma unroll
        for (int i = 0; i < 8; i++) {
            unsigned h = (ws[i >> 1] >> ((i & 1) * 16)) & 0xFFFFu;
            unsigned k16 = (h & 0x8000u) ? (~h & 0xFFFFu) : (h | 0x8000u);
            unsigned bit = (wbits >> ((n0 + i) & 31)) & 1u;
            keys[j * 8 + i] = bit ? (k16 << 16) : 0xFFFF0000u;
        }
    }

    int nv = g_nv[b], kT = g_kk[b];

#pragma unroll
    for (int i = 0; i < 32; i++) planes[i] = keys[i];
    transpose32(planes);
    unsigned T2 = radix_rank16(planes, nv - kT - 1);
    unsigned T1 = 0;
    if (kT > 0) T1 = radix_rank16(planes, kT - 1);

    int c1 = 0, c2 = 0;
    float s1 = 0.f, s2 = 0.f;
#pragma unroll
    for (int i = 0; i < 32; i++) {
        unsigned kv = keys[i];
        float fv = keyToFloat16(kv);
        if (kT > 0 && kv < T1) { c1++; s1 += fv; }
        if (kv < T2) { c2++; s2 += fv; }
    }
    c1 = __reduce_add_sync(0xFFFFFFFFu, c1);
    c2 = __reduce_add_sync(0xFFFFFFFFu, c2);
#pragma unroll
    for (int o = 16; o; o >>= 1) {
        s1 += __shfl_xor_sync(0xFFFFFFFFu, s1, o);
        s2 += __shfl_xor_sync(0xFFFFFFFFu, s2, o);
    }
    float Sk = (kT > 0) ? (s1 + (float)(kT - c1) * keyToFloat16(T1)) : 0.f;
    float Snk = s2 + (float)((nv - kT) - c2) * keyToFloat16(T2);
    if (lane == 0) g_agg[warp] = (Snk - Sk) / (float)(nv - 2 * kT);
}

// ------------------------- decode MLP -------------------------
__global__ void decode1_kernel(const float* __restrict__ W3, const float* __restrict__ b3) {
    __shared__ float sa[8][1024];
    int h = blockIdx.x * 128 + threadIdx.x;
    int bg = blockIdx.y * 8;
    for (int i = threadIdx.x; i < 8 * 1024; i += 128)
        sa[i >> 10][i & 1023] = g_agg[(bg + (i >> 10)) * 1024 + (i & 1023)];
    __syncthreads();
    float accv[8];
#pragma unroll
    for (int ii = 0; ii < 8; ii++) accv[ii] = 0.f;
    for (int k2 = 0; k2 < 1024; k2++) {
        float w = W3[(size_t)k2 * 1024 + h];
#pragma unroll
        for (int ii = 0; ii < 8; ii++) accv[ii] += sa[ii][k2] * w;
    }
    float bb = b3[h];
#pragma unroll
    for (int ii = 0; ii < 8; ii++) g_T[(bg + ii) * 1024 + h] = fmaxf(accv[ii] + bb, 0.f);
}

__global__ void decode2_kernel(const float* __restrict__ W4, const float* __restrict__ b4,
                               float* __restrict__ out) {
    int gw = blockIdx.x * 8 + (threadIdx.x >> 5);
    int lane = threadIdx.x & 31;
    if (gw >= 640) return;
    int b = gw / 10, o = gw - 10 * b;
    float acc = 0.f;
#pragma unroll
    for (int i = 0; i < 32; i++) {
        int kidx = i * 32 + lane;
        acc += g_T[b * 1024 + kidx] * W4[(size_t)kidx * 10 + o];
    }
#pragma unroll
    for (int oo = 16; oo; oo >>= 1) acc += __shfl_xor_sync(0xFFFFFFFFu, acc, oo);
    if (lane == 0) out[b * 10 + o] = acc + b4[o];
}

// ------------------------- launch -------------------------
extern "C" void kernel_launch(void* const* d_in, const int* in_sizes, int n_in,
                              void* d_out, int out_size) {
    const float* X = (const float*)d_in[0];
    const float* mask = (const float*)d_in[1];
    const float* W1 = (const float*)d_in[2];
    const float* b1 = (const float*)d_in[3];
    const float* W2 = (const float*)d_in[4];
    const float* b2 = (const float*)d_in[5];
    const float* W3 = (const float*)d_in[6];
    const float* b3 = (const float*)d_in[7];
    const float* W4 = (const float*)d_in[8];
    const float* b4 = (const float*)d_in[9];
    float* out = (float*)d_out;

    void *pXh, *pW1T, *pW2T, *pH1, *pET;
    cudaGetSymbolAddress(&pXh, g_Xh);
    cudaGetSymbolAddress(&pW1T, g_W1T);
    cudaGetSymbolAddress(&pW2T, g_W2T);
    cudaGetSymbolAddress(&pH1, g_H1);
    cudaGetSymbolAddress(&pET, g_ET);

    cudaFuncSetAttribute(gemm_fp16<true, false>, cudaFuncAttributeMaxDynamicSharedMemorySize, GEMM_SMEM);
    cudaFuncSetAttribute(gemm_fp16<false, true>, cudaFuncAttributeMaxDynamicSharedMemorySize, GEMM_SMEM);

    castX_kernel<<<32768, 256>>>(X);
    transW_kernel<<<dim3(32, 16), dim3(32, 8)>>>(W1, (__half*)pW1T, DIN_);
    transW_kernel<<<dim3(32, 32), dim3(32, 8)>>>(W2, (__half*)pW2T, DH_);
    nvbits_kernel<<<64, 1024>>>(mask);

    // GEMM1: H1[m,h] = relu(X[m,:]·W1T[h,:] + b1[h])
    gemm_fp16<true, false><<<dim3(DH_ / BN, (B_ * N_) / BM, 1), 256, GEMM_SMEM>>>(
        (const __half*)pXh, (const __half*)pW1T, b1, (__half*)pH1,
        DIN_, DH_, 0, 0);

    // GEMM2 (transposed out): ET[b][h][n] = W2T[h,:]·H1[b][n,:] + b2[h]
    gemm_fp16<false, true><<<dim3(N_ / BN, DH_ / BM, B_), 256, GEMM_SMEM>>>(
        (const __half*)pW2T, (const __half*)pH1, b2, (__half*)pET,
        DH_, N_, (size_t)N_ * DH_, (size_t)DH_ * N_);

    select_kernel<<<(B_ * DH_) / 8, 256>>>();
    decode1_kernel<<<dim3(8, 8), 128>>>(W3, b3);
    decode2_kernel<<<80, 256>>>(W4, b4, out);
}

// round 8
// speedup vs baseline: 1.5677x; 1.1270x over previous
#include <cuda_runtime.h>
#include <cuda_fp16.h>
#include <cstdint>
#include <cstddef>

#define B_    64
#define N_    1024
#define DIN_  512
#define DH_   1024

#define BM 128
#define BN 128
#define BK 64
#define SSTRIDE 72           // fp16 elems per smem row: 64 data + 8 pad (144B)
#define TS 3
#define STAGE_HALFS ((BM + BN) * SSTRIDE)   // 18432 halfs = 36864 B
#define GEMM_SMEM (TS * STAGE_HALFS * 2)    // 110592 B

// ------------------------- static device scratch -------------------------
__device__ __half g_Xh[(size_t)B_ * N_ * DIN_];
__device__ __half g_W1T[(size_t)DH_ * DIN_];
__device__ __half g_W2T[(size_t)DH_ * DH_];
__device__ __half g_H1[(size_t)B_ * N_ * DH_];
__device__ __half g_ET[(size_t)B_ * DH_ * N_];
__device__ float  g_agg[B_ * DH_];
__device__ float  g_T[B_ * DH_];
__device__ int    g_nv[B_];
__device__ int    g_kk[B_];
__device__ unsigned g_bits[B_ * (N_ / 32)];

// ------------------------- helpers -------------------------
__device__ __forceinline__ float keyToFloat16(unsigned k32) {
    unsigned t = k32 >> 16;
    unsigned short b = (t & 0x8000u) ? (unsigned short)(t ^ 0x8000u)
                                     : (unsigned short)(~t & 0xFFFFu);
    return __half2float(__ushort_as_half(b));
}

__device__ __forceinline__ void mma16816(float* c, const uint32_t* a, uint32_t b0, uint32_t b1) {
    asm volatile(
        "mma.sync.aligned.m16n8k16.row.col.f32.f16.f16.f32 "
        "{%0,%1,%2,%3},{%4,%5,%6,%7},{%8,%9},{%0,%1,%2,%3};\n"
        : "+f"(c[0]), "+f"(c[1]), "+f"(c[2]), "+f"(c[3])
        : "r"(a[0]), "r"(a[1]), "r"(a[2]), "r"(a[3]), "r"(b0), "r"(b1));
}
__device__ __forceinline__ void ldmat4(uint32_t* r, uint32_t addr) {
    asm volatile("ldmatrix.sync.aligned.m8n8.x4.shared.b16 {%0,%1,%2,%3},[%4];\n"
                 : "=r"(r[0]), "=r"(r[1]), "=r"(r[2]), "=r"(r[3])
                 : "r"(addr));
}
#define CP16(dst, src) asm volatile("cp.async.cg.shared.global [%0],[%1],16;\n" ::"r"(dst), "l"(src))

// 32x32 bit transpose (Hacker's Delight), involution.
template <int J>
__device__ __forceinline__ void tstep(unsigned* A, unsigned m) {
#pragma unroll
    for (int k0 = 0; k0 < 16; k0++) {
        int k = ((k0 & ~(J - 1)) << 1) | (k0 & (J - 1));
        unsigned t = (A[k] ^ (A[k + J] >> J)) & m;
        A[k] ^= t;
        A[k + J] ^= (t << J);
    }
}
__device__ __forceinline__ void transpose32(unsigned* A) {
    tstep<16>(A, 0x0000FFFFu);
    tstep<8>(A, 0x00FF00FFu);
    tstep<4>(A, 0x0F0F0F0Fu);
    tstep<2>(A, 0x33333333u);
    tstep<1>(A, 0x55555555u);
}
// planes = bit-transposed keys (bits 31..16). Rank r over the warp's 1024 keys.
__device__ __forceinline__ unsigned radix_rank16(const unsigned* planes, int r) {
    unsigned C = 0xFFFFFFFFu, prefix = 0u;
#pragma unroll
    for (int bit = 31; bit >= 16; --bit) {
        unsigned P = planes[31 - bit];
        unsigned zeros = C & ~P;
        int c0 = __reduce_add_sync(0xFFFFFFFFu, __popc(zeros));
        if (r < c0) {
            C = zeros;
        } else {
            r -= c0;
            C &= P;
            prefix |= (1u << bit);
        }
    }
    return prefix;
}

// ------------------------- prep kernels -------------------------
__global__ void castX_kernel(const float* __restrict__ X) {
    size_t i = (size_t)blockIdx.x * blockDim.x + threadIdx.x;
    float4 v = ((const float4*)X)[i];
    __half2* p = (__half2*)&g_Xh[4 * i];
    p[0] = __floats2half2_rn(v.x, v.y);
    p[1] = __floats2half2_rn(v.z, v.w);
}

__global__ void transW_kernel(const float* __restrict__ W, __half* __restrict__ WT, int Krows) {
    __shared__ float tile[32][33];
    int tx = threadIdx.x, ty = threadIdx.y;
    int x = blockIdx.x * 32 + tx;
#pragma unroll
    for (int i = 0; i < 32; i += 8) {
        int y = blockIdx.y * 32 + ty + i;
        tile[ty + i][tx] = W[(size_t)y * DH_ + x];
    }
    __syncthreads();
    int xo = blockIdx.y * 32 + tx;
#pragma unroll
    for (int i = 0; i < 32; i += 8) {
        int yo = blockIdx.x * 32 + ty + i;
        WT[(size_t)yo * Krows + xo] = __float2half_rn(tile[tx][ty + i]);
    }
}

__global__ void nvbits_kernel(const float* __restrict__ mask) {
    int b = blockIdx.x, t = threadIdx.x;
    int v = mask[(size_t)b * N_ + t] > 0.0f;
    unsigned word = __ballot_sync(0xFFFFFFFFu, v);
    __shared__ int cnt;
    if (t == 0) cnt = 0;
    __syncthreads();
    if ((t & 31) == 0) {
        g_bits[b * 32 + (t >> 5)] = word;
        atomicAdd(&cnt, __popc(word));
    }
    __syncthreads();
    if (t == 0) {
        g_nv[b] = cnt;
        g_kk[b] = (int)((float)cnt * 0.1f);
    }
}

// ------------------------- main GEMM (fp16 MMA, fp32 accum) -------------
// A [.., K] row-major; B [.., K] row-major (col-major MMA operand).
// Block 128x128, 8 warps of 64x32, BK=64, 3-stage cp.async pipeline.
// SKIP_MODE 0: none; 1: skip if (mBase&1023) >= nv[mBase>>10] (GEMM1);
//           2: skip if nBase >= nv[blockIdx.z] (GEMM2).
template <bool RELU, bool BIAS_BY_ROW, int SKIP_MODE>
__global__ void __launch_bounds__(256, 2) gemm_fp16(
    const __half* __restrict__ A, const __half* __restrict__ B,
    const float* __restrict__ bias, __half* __restrict__ out,
    int K, int N, size_t zB, size_t zC) {
    extern __shared__ __half sm[];

    const int mBase = blockIdx.y * BM, nBase = blockIdx.x * BN;
    if (SKIP_MODE == 1) {
        if ((mBase & (N_ - 1)) >= g_nv[mBase >> 10]) return;
    } else if (SKIP_MODE == 2) {
        if (nBase >= g_nv[blockIdx.z]) return;
    }

    B += (size_t)blockIdx.z * zB;
    out += (size_t)blockIdx.z * zC;

    const int tid = threadIdx.x;
    const int lane = tid & 31;
    const int wid = tid >> 5;
    const int wm = (wid >> 2) * 64;
    const int wn = (wid & 3) * 32;
    const int gq = lane >> 2, tg = lane & 3;
    const int KT = K / BK;

    float acc[4][4][4];
#pragma unroll
    for (int a = 0; a < 4; a++)
#pragma unroll
        for (int b = 0; b < 4; b++)
#pragma unroll
            for (int c = 0; c < 4; c++) acc[a][b][c] = 0.f;

    // stage layout: rows 0..127 = A tile, rows 128..255 = B tile
    auto load = [&](int kt, int s) {
        __half* sa = sm + s * STAGE_HALFS;
        int k0 = kt * BK;
#pragma unroll
        for (int p = 0; p < 8; p++) {
            int v = tid + 256 * p;      // 0..2047 -> 256 rows x 8 chunks of 16B
            int row = v >> 3;
            int cv = (v & 7) * 8;
            uint32_t d = (uint32_t)__cvta_generic_to_shared(sa + row * SSTRIDE + cv);
            const __half* src = (row < BM) ? (A + (size_t)(mBase + row) * K + k0 + cv)
                                           : (B + (size_t)(nBase + row - BM) * K + k0 + cv);
            CP16(d, src);
        }
        asm volatile("cp.async.commit_group;\n");
    };

    load(0, 0);
    if (KT > 1) load(1, 1);
    for (int kt = 0; kt < KT; kt++) {
        int s = kt % TS;
        if (kt + 1 < KT) {
            asm volatile("cp.async.wait_group 1;\n");
        } else {
            asm volatile("cp.async.wait_group 0;\n");
        }
        __syncthreads();
        if (kt + 2 < KT) load(kt + 2, (kt + 2) % TS);

        const __half* sa = sm + s * STAGE_HALFS;
        const __half* sb = sa + BM * SSTRIDE;
#pragma unroll
        for (int kk = 0; kk < BK; kk += 16) {
            uint32_t af[4][4];
#pragma unroll
            for (int mi = 0; mi < 4; mi++) {
                uint32_t ad = (uint32_t)__cvta_generic_to_shared(
                    sa + (wm + mi * 16 + (lane & 15)) * SSTRIDE + kk + (lane >> 4) * 8);
                ldmat4(af[mi], ad);
            }
#pragma unroll
            for (int ni = 0; ni < 4; ni++) {
                const __half* bp = sb + (wn + ni * 8 + gq) * SSTRIDE + kk + 2 * tg;
                uint32_t b0 = *(const uint32_t*)bp;
                uint32_t b1v = *(const uint32_t*)(bp + 8);
#pragma unroll
                for (int mi = 0; mi < 4; mi++) mma16816(acc[mi][ni], af[mi], b0, b1v);
            }
        }
    }

#pragma unroll
    for (int mi = 0; mi < 4; mi++) {
        int r0 = mBase + wm + mi * 16 + gq;
        float bvR0 = 0.f, bvR1 = 0.f;
        if (BIAS_BY_ROW) { bvR0 = bias[r0]; bvR1 = bias[r0 + 8]; }
#pragma unroll
        for (int ni = 0; ni < 4; ni++) {
            int col = nBase + wn + ni * 8 + 2 * tg;
            float v00, v01, v10, v11;
            if (BIAS_BY_ROW) {
                v00 = acc[mi][ni][0] + bvR0; v01 = acc[mi][ni][1] + bvR0;
                v10 = acc[mi][ni][2] + bvR1; v11 = acc[mi][ni][3] + bvR1;
            } else {
                float bv0 = bias[col], bv1 = bias[col + 1];
                v00 = acc[mi][ni][0] + bv0; v01 = acc[mi][ni][1] + bv1;
                v10 = acc[mi][ni][2] + bv0; v11 = acc[mi][ni][3] + bv1;
            }
            if (RELU) {
                v00 = fmaxf(v00, 0.f); v01 = fmaxf(v01, 0.f);
                v10 = fmaxf(v10, 0.f); v11 = fmaxf(v11, 0.f);
            }
            *(__half2*)(out + (size_t)r0 * N + col) = __floats2half2_rn(v00, v01);
            *(__half2*)(out + (size_t)(r0 + 8) * N + col) = __floats2half2_rn(v10, v11);
        }
    }
}

// ------------------------- trimmed-mean select -------------------------
__global__ void __launch_bounds__(256) select_kernel() {
    int warp = (blockIdx.x << 3) + (threadIdx.x >> 5);  // b*1024 + h
    int lane = threadIdx.x & 31;
    int b = warp >> 10;
    const __half* col = g_ET + ((size_t)warp << 10);

    int nv = g_nv[b], kT = g_kk[b];

    unsigned keys[32], planes[32];
#pragma unroll
    for (int j = 0; j < 4; j++) {
        int n0 = j * 256 + lane * 8;
        if (j * 256 >= nv) {  // whole chunk beyond valid prefix
#pragma unroll
            for (int i = 0; i < 8; i++) keys[j * 8 + i] = 0xFFFF0000u;
            continue;
        }
        uint4 v = *(const uint4*)(col + n0);
        unsigned wbits = g_bits[(b << 5) + (n0 >> 5)];
        unsigned ws[4] = {v.x, v.y, v.z, v.w};
#pragma unroll
        for (int i = 0; i < 8; i++) {
            unsigned h = (ws[i >> 1] >> ((i & 1) * 16)) & 0xFFFFu;
            unsigned k16 = (h & 0x8000u) ? (~h & 0xFFFFu) : (h | 0x8000u);
            unsigned bit = (wbits >> ((n0 + i) & 31)) & 1u;
            keys[j * 8 + i] = bit ? (k16 << 16) : 0xFFFF0000u;
        }
    }

#pragma unroll
    for (int i = 0; i < 32; i++) planes[i] = keys[i];
    transpose32(planes);
    unsigned T2 = radix_rank16(planes, nv - kT - 1);
    unsigned T1 = 0;
    if (kT > 0) T1 = radix_rank16(planes, kT - 1);

    int c1 = 0, c2 = 0;
    float s1 = 0.f, s2 = 0.f;
#pragma unroll
    for (int i = 0; i < 32; i++) {
        unsigned kv = keys[i];
        float fv = keyToFloat16(kv);
        if (kT > 0 && kv < T1) { c1++; s1 += fv; }
        if (kv < T2) { c2++; s2 += fv; }
    }
    c1 = __reduce_add_sync(0xFFFFFFFFu, c1);
    c2 = __reduce_add_sync(0xFFFFFFFFu, c2);
#pragma unroll
    for (int o = 16; o; o >>= 1) {
        s1 += __shfl_xor_sync(0xFFFFFFFFu, s1, o);
        s2 += __shfl_xor_sync(0xFFFFFFFFu, s2, o);
    }
    float Sk = (kT > 0) ? (s1 + (float)(kT - c1) * keyToFloat16(T1)) : 0.f;
    float Snk = s2 + (float)((nv - kT) - c2) * keyToFloat16(T2);
    if (lane == 0) g_agg[warp] = (Snk - Sk) / (float)(nv - 2 * kT);
}

// ------------------------- decode MLP -------------------------
__global__ void decode1_kernel(const float* __restrict__ W3, const float* __restrict__ b3) {
    __shared__ float sa[8][1024];
    int h = blockIdx.x * 128 + threadIdx.x;
    int bg = blockIdx.y * 8;
    for (int i = threadIdx.x; i < 8 * 1024; i += 128)
        sa[i >> 10][i & 1023] = g_agg[(bg + (i >> 10)) * 1024 + (i & 1023)];
    __syncthreads();
    float accv[8];
#pragma unroll
    for (int ii = 0; ii < 8; ii++) accv[ii] = 0.f;
    for (int k2 = 0; k2 < 1024; k2++) {
        float w = W3[(size_t)k2 * 1024 + h];
#pragma unroll
        for (int ii = 0; ii < 8; ii++) accv[ii] += sa[ii][k2] * w;
    }
    float bb = b3[h];
#pragma unroll
    for (int ii = 0; ii < 8; ii++) g_T[(bg + ii) * 1024 + h] = fmaxf(accv[ii] + bb, 0.f);
}

__global__ void decode2_kernel(const float* __restrict__ W4, const float* __restrict__ b4,
                               float* __restrict__ out) {
    int gw = blockIdx.x * 8 + (threadIdx.x >> 5);
    int lane = threadIdx.x & 31;
    if (gw >= 640) return;
    int b = gw / 10, o = gw - 10 * b;
    float acc = 0.f;
#pragma unroll
    for (int i = 0; i < 32; i++) {
        int kidx = i * 32 + lane;
        acc += g_T[b * 1024 + kidx] * W4[(size_t)kidx * 10 + o];
    }
#pragma unroll
    for (int oo = 16; oo; oo >>= 1) acc += __shfl_xor_sync(0xFFFFFFFFu, acc, oo);
    if (lane == 0) out[b * 10 + o] = acc + b4[o];
}

// ------------------------- launch -------------------------
extern "C" void kernel_launch(void* const* d_in, const int* in_sizes, int n_in,
                              void* d_out, int out_size) {
    const float* X = (const float*)d_in[0];
    const float* mask = (const float*)d_in[1];
    const float* W1 = (const float*)d_in[2];
    const float* b1 = (const float*)d_in[3];
    const float* W2 = (const float*)d_in[4];
    const float* b2 = (const float*)d_in[5];
    const float* W3 = (const float*)d_in[6];
    const float* b3 = (const float*)d_in[7];
    const float* W4 = (const float*)d_in[8];
    const float* b4 = (const float*)d_in[9];
    float* out = (float*)d_out;

    void *pXh, *pW1T, *pW2T, *pH1, *pET;
    cudaGetSymbolAddress(&pXh, g_Xh);
    cudaGetSymbolAddress(&pW1T, g_W1T);
    cudaGetSymbolAddress(&pW2T, g_W2T);
    cudaGetSymbolAddress(&pH1, g_H1);
    cudaGetSymbolAddress(&pET, g_ET);

    cudaFuncSetAttribute(gemm_fp16<true, false, 1>, cudaFuncAttributeMaxDynamicSharedMemorySize, GEMM_SMEM);
    cudaFuncSetAttribute(gemm_fp16<false, true, 2>, cudaFuncAttributeMaxDynamicSharedMemorySize, GEMM_SMEM);

    castX_kernel<<<32768, 256>>>(X);
    transW_kernel<<<dim3(32, 16), dim3(32, 8)>>>(W1, (__half*)pW1T, DIN_);
    transW_kernel<<<dim3(32, 32), dim3(32, 8)>>>(W2, (__half*)pW2T, DH_);
    nvbits_kernel<<<64, 1024>>>(mask);

    // GEMM1: H1[m,h] = relu(X[m,:]·W1T[h,:] + b1[h]); skip fully-invalid m-tiles
    gemm_fp16<true, false, 1><<<dim3(DH_ / BN, (B_ * N_) / BM, 1), 256, GEMM_SMEM>>>(
        (const __half*)pXh, (const __half*)pW1T, b1, (__half*)pH1,
        DIN_, DH_, 0, 0);

    // GEMM2 (transposed out): ET[b][h][n] = W2T[h,:]·H1[b][n,:] + b2[h]; skip invalid n-tiles
    gemm_fp16<false, true, 2><<<dim3(N_ / BN, DH_ / BM, B_), 256, GEMM_SMEM>>>(
        (const __half*)pW2T, (const __half*)pH1, b2, (__half*)pET,
        DH_, N_, (size_t)N_ * DH_, (size_t)DH_ * N_);

    select_kernel<<<(B_ * DH_) / 8, 256>>>();
    decode1_kernel<<<dim3(8, 8), 128>>>(W3, b3);
    decode2_kernel<<<80, 256>>>(W4, b4, out);
}

// round 9
// speedup vs baseline: 1.5989x; 1.0199x over previous
#include <cuda_runtime.h>
#include <cuda_fp16.h>
#include <cstdint>
#include <cstddef>

#define B_    64
#define N_    1024
#define DIN_  512
#define DH_   1024

#define BM 128
#define BN 128
#define BK 64
#define SSTRIDE 72           // fp16 elems per smem row: 64 data + 8 pad (144B)
#define TS 3
#define STAGE_HALFS ((BM + BN) * SSTRIDE)   // 18432 halfs = 36864 B
#define GEMM_SMEM (TS * STAGE_HALFS * 2)    // 110592 B

// prep kernel block partition
#define PREP_CAST_BLKS 32768
#define PREP_W1_BASE   PREP_CAST_BLKS
#define PREP_W1_BLKS   512
#define PREP_W2_BASE   (PREP_W1_BASE + PREP_W1_BLKS)
#define PREP_W2_BLKS   1024
#define PREP_NV_BASE   (PREP_W2_BASE + PREP_W2_BLKS)
#define PREP_NV_BLKS   64
#define PREP_TOTAL     (PREP_NV_BASE + PREP_NV_BLKS)

// ------------------------- static device scratch -------------------------
__device__ __half g_Xh[(size_t)B_ * N_ * DIN_];
__device__ __half g_W1T[(size_t)DH_ * DIN_];
__device__ __half g_W2T[(size_t)DH_ * DH_];
__device__ __half g_H1[(size_t)B_ * N_ * DH_];
__device__ __half g_ET[(size_t)B_ * DH_ * N_];
__device__ float  g_agg[B_ * DH_];
__device__ float  g_T[B_ * DH_];
__device__ int    g_nv[B_];
__device__ int    g_kk[B_];
__device__ unsigned g_bits[B_ * (N_ / 32)];

// ------------------------- helpers -------------------------
__device__ __forceinline__ float keyToFloat16(unsigned k32) {
    unsigned t = k32 >> 16;
    unsigned short b = (t & 0x8000u) ? (unsigned short)(t ^ 0x8000u)
                                     : (unsigned short)(~t & 0xFFFFu);
    return __half2float(__ushort_as_half(b));
}

__device__ __forceinline__ void mma16816(float* c, const uint32_t* a, uint32_t b0, uint32_t b1) {
    asm volatile(
        "mma.sync.aligned.m16n8k16.row.col.f32.f16.f16.f32 "
        "{%0,%1,%2,%3},{%4,%5,%6,%7},{%8,%9},{%0,%1,%2,%3};\n"
        : "+f"(c[0]), "+f"(c[1]), "+f"(c[2]), "+f"(c[3])
        : "r"(a[0]), "r"(a[1]), "r"(a[2]), "r"(a[3]), "r"(b0), "r"(b1));
}
__device__ __forceinline__ void ldmat4(uint32_t* r, uint32_t addr) {
    asm volatile("ldmatrix.sync.aligned.m8n8.x4.shared.b16 {%0,%1,%2,%3},[%4];\n"
                 : "=r"(r[0]), "=r"(r[1]), "=r"(r[2]), "=r"(r[3])
                 : "r"(addr));
}
#define CP16(dst, src) asm volatile("cp.async.cg.shared.global [%0],[%1],16;\n" ::"r"(dst), "l"(src))

// 32x32 bit transpose (Hacker's Delight), involution.
template <int J>
__device__ __forceinline__ void tstep(unsigned* A, unsigned m) {
#pragma unroll
    for (int k0 = 0; k0 < 16; k0++) {
        int k = ((k0 & ~(J - 1)) << 1) | (k0 & (J - 1));
        unsigned t = (A[k] ^ (A[k + J] >> J)) & m;
        A[k] ^= t;
        A[k + J] ^= (t << J);
    }
}
__device__ __forceinline__ void transpose32(unsigned* A) {
    tstep<16>(A, 0x0000FFFFu);
    tstep<8>(A, 0x00FF00FFu);
    tstep<4>(A, 0x0F0F0F0Fu);
    tstep<2>(A, 0x33333333u);
    tstep<1>(A, 0x55555555u);
}
// planes = bit-transposed keys (bits 31..16). Rank r over the warp's 1024 keys.
__device__ __forceinline__ unsigned radix_rank16(const unsigned* planes, int r) {
    unsigned C = 0xFFFFFFFFu, prefix = 0u;
#pragma unroll
    for (int bit = 31; bit >= 16; --bit) {
        unsigned P = planes[31 - bit];
        unsigned zeros = C & ~P;
        int c0 = __reduce_add_sync(0xFFFFFFFFu, __popc(zeros));
        if (r < c0) {
            C = zeros;
        } else {
            r -= c0;
            C &= P;
            prefix |= (1u << bit);
        }
    }
    return prefix;
}

// ------------------------- fused prep kernel -------------------------
// blocks [0, 32768): castX (2 rows per block, skip invalid rows)
// blocks [32768, 33280): transW1 ; [33280, 34304): transW2 ; [34304, 34368): nvbits
__global__ void __launch_bounds__(256) prep_kernel(
    const float* __restrict__ X, const float* __restrict__ mask,
    const float* __restrict__ W1, const float* __restrict__ W2) {
    __shared__ float tile[32][33];
    const int bid = blockIdx.x;
    const int tid = threadIdx.x;

    if (bid < PREP_CAST_BLKS) {
        // cast X rows to fp16; row = global (b*1024+n); prefix mask => skip invalid
        int i = bid * 256 + tid;       // float4 index
        int row = i >> 7;              // 128 float4 per row (512 floats)
        if (mask[row] > 0.0f) {
            float4 v = ((const float4*)X)[i];
            __half2* p = (__half2*)&g_Xh[4 * (size_t)i];
            p[0] = __floats2half2_rn(v.x, v.y);
            p[1] = __floats2half2_rn(v.z, v.w);
        }
        return;
    }

    if (bid < PREP_NV_BASE) {
        // transpose W [Krows,1024] f32 -> WT [1024,Krows] fp16
        const float* W;
        __half* WT;
        int Krows, local;
        if (bid < PREP_W2_BASE) {
            local = bid - PREP_W1_BASE;
            W = W1;
            Krows = DIN_;
            WT = g_W1T;
        } else {
            local = bid - PREP_W2_BASE;
            W = W2;
            Krows = DH_;
            WT = g_W2T;
        }
        int bx = local & 31, by = local >> 5;
        int tx = tid & 31, ty = tid >> 5;  // 32 x 8
        int x = bx * 32 + tx;
#pragma unroll
        for (int i = 0; i < 32; i += 8) {
            int y = by * 32 + ty + i;
            tile[ty + i][tx] = W[(size_t)y * DH_ + x];
        }
        __syncthreads();
        int xo = by * 32 + tx;
#pragma unroll
        for (int i = 0; i < 32; i += 8) {
            int yo = bx * 32 + ty + i;
            WT[(size_t)yo * Krows + xo] = __float2half_rn(tile[tx][ty + i]);
        }
        return;
    }

    // nvbits: one block per batch, 256 threads, 4 words per warp
    {
        int b = bid - PREP_NV_BASE;
        __shared__ int cnt;
        if (tid == 0) cnt = 0;
        __syncthreads();
        int lane = tid & 31, w = tid >> 5;
        int local = 0;
#pragma unroll
        for (int j = 0; j < 4; j++) {
            int widx = w + 8 * j;
            int n = widx * 32 + lane;
            int v = mask[(size_t)b * N_ + n] > 0.0f;
            unsigned word = __ballot_sync(0xFFFFFFFFu, v);
            if (lane == 0) {
                g_bits[b * 32 + widx] = word;
                local += __popc(word);
            }
        }
        if (lane == 0 && local) atomicAdd(&cnt, local);
        __syncthreads();
        if (tid == 0) {
            g_nv[b] = cnt;
            g_kk[b] = (int)((float)cnt * 0.1f);
        }
    }
}

// ------------------------- main GEMM (fp16 MMA, fp32 accum) -------------
// A [.., K] row-major; B [.., K] row-major (col-major MMA operand).
// Block 128x128, 8 warps of 64x32, BK=64, 3-stage cp.async pipeline.
// SKIP_MODE 1: skip if (mBase&1023) >= nv[mBase>>10] (GEMM1);
//           2: skip if nBase >= nv[blockIdx.z] (GEMM2).
template <bool RELU, bool BIAS_BY_ROW, int SKIP_MODE>
__global__ void __launch_bounds__(256, 2) gemm_fp16(
    const __half* __restrict__ A, const __half* __restrict__ B,
    const float* __restrict__ bias, __half* __restrict__ out,
    int K, int N, size_t zB, size_t zC) {
    extern __shared__ __half sm[];

    const int mBase = blockIdx.y * BM, nBase = blockIdx.x * BN;
    if (SKIP_MODE == 1) {
        if ((mBase & (N_ - 1)) >= g_nv[mBase >> 10]) return;
    } else if (SKIP_MODE == 2) {
        if (nBase >= g_nv[blockIdx.z]) return;
    }

    B += (size_t)blockIdx.z * zB;
    out += (size_t)blockIdx.z * zC;

    const int tid = threadIdx.x;
    const int lane = tid & 31;
    const int wid = tid >> 5;
    const int wm = (wid >> 2) * 64;
    const int wn = (wid & 3) * 32;
    const int gq = lane >> 2, tg = lane & 3;
    const int KT = K / BK;

    float acc[4][4][4];
#pragma unroll
    for (int a = 0; a < 4; a++)
#pragma unroll
        for (int b = 0; b < 4; b++)
#pragma unroll
            for (int c = 0; c < 4; c++) acc[a][b][c] = 0.f;

    auto load = [&](int kt, int s) {
        __half* sa = sm + s * STAGE_HALFS;
        int k0 = kt * BK;
#pragma unroll
        for (int p = 0; p < 8; p++) {
            int v = tid + 256 * p;
            int row = v >> 3;
            int cv = (v & 7) * 8;
            uint32_t d = (uint32_t)__cvta_generic_to_shared(sa + row * SSTRIDE + cv);
            const __half* src = (row < BM) ? (A + (size_t)(mBase + row) * K + k0 + cv)
                                           : (B + (size_t)(nBase + row - BM) * K + k0 + cv);
            CP16(d, src);
        }
        asm volatile("cp.async.commit_group;\n");
    };

    load(0, 0);
    if (KT > 1) load(1, 1);
    for (int kt = 0; kt < KT; kt++) {
        int s = kt % TS;
        if (kt + 1 < KT) {
            asm volatile("cp.async.wait_group 1;\n");
        } else {
            asm volatile("cp.async.wait_group 0;\n");
        }
        __syncthreads();
        if (kt + 2 < KT) load(kt + 2, (kt + 2) % TS);

        const __half* sa = sm + s * STAGE_HALFS;
        const __half* sb = sa + BM * SSTRIDE;
#pragma unroll
        for (int kk = 0; kk < BK; kk += 16) {
            uint32_t af[4][4];
#pragma unroll
            for (int mi = 0; mi < 4; mi++) {
                uint32_t ad = (uint32_t)__cvta_generic_to_shared(
                    sa + (wm + mi * 16 + (lane & 15)) * SSTRIDE + kk + (lane >> 4) * 8);
                ldmat4(af[mi], ad);
            }
#pragma unroll
            for (int ni = 0; ni < 4; ni++) {
                const __half* bp = sb + (wn + ni * 8 + gq) * SSTRIDE + kk + 2 * tg;
                uint32_t b0 = *(const uint32_t*)bp;
                uint32_t b1v = *(const uint32_t*)(bp + 8);
#pragma unroll
                for (int mi = 0; mi < 4; mi++) mma16816(acc[mi][ni], af[mi], b0, b1v);
            }
        }
    }

#pragma unroll
    for (int mi = 0; mi < 4; mi++) {
        int r0 = mBase + wm + mi * 16 + gq;
        float bvR0 = 0.f, bvR1 = 0.f;
        if (BIAS_BY_ROW) { bvR0 = bias[r0]; bvR1 = bias[r0 + 8]; }
#pragma unroll
        for (int ni = 0; ni < 4; ni++) {
            int col = nBase + wn + ni * 8 + 2 * tg;
            float v00, v01, v10, v11;
            if (BIAS_BY_ROW) {
                v00 = acc[mi][ni][0] + bvR0; v01 = acc[mi][ni][1] + bvR0;
                v10 = acc[mi][ni][2] + bvR1; v11 = acc[mi][ni][3] + bvR1;
            } else {
                float bv0 = bias[col], bv1 = bias[col + 1];
                v00 = acc[mi][ni][0] + bv0; v01 = acc[mi][ni][1] + bv1;
                v10 = acc[mi][ni][2] + bv0; v11 = acc[mi][ni][3] + bv1;
            }
            if (RELU) {
                v00 = fmaxf(v00, 0.f); v01 = fmaxf(v01, 0.f);
                v10 = fmaxf(v10, 0.f); v11 = fmaxf(v11, 0.f);
            }
            *(__half2*)(out + (size_t)r0 * N + col) = __floats2half2_rn(v00, v01);
            *(__half2*)(out + (size_t)(r0 + 8) * N + col) = __floats2half2_rn(v10, v11);
        }
    }
}

// ------------------------- trimmed-mean select -------------------------
__global__ void __launch_bounds__(256) select_kernel() {
    int warp = (blockIdx.x << 3) + (threadIdx.x >> 5);  // b*1024 + h
    int lane = threadIdx.x & 31;
    int b = warp >> 10;
    const __half* col = g_ET + ((size_t)warp << 10);

    int nv = g_nv[b], kT = g_kk[b];

    unsigned keys[32], planes[32];
#pragma unroll
    for (int j = 0; j < 4; j++) {
        int n0 = j * 256 + lane * 8;
        if (j * 256 >= nv) {
#pragma unroll
            for (int i = 0; i < 8; i++) keys[j * 8 + i] = 0xFFFF0000u;
            continue;
        }
        uint4 v = *(const uint4*)(col + n0);
        unsigned wbits = g_bits[(b << 5) + (n0 >> 5)];
        unsigned ws[4] = {v.x, v.y, v.z, v.w};
#pragma unroll
        for (int i = 0; i < 8; i++) {
            unsigned h = (ws[i >> 1] >> ((i & 1) * 16)) & 0xFFFFu;
            unsigned k16 = (h & 0x8000u) ? (~h & 0xFFFFu) : (h | 0x8000u);
            unsigned bit = (wbits >> ((n0 + i) & 31)) & 1u;
            keys[j * 8 + i] = bit ? (k16 << 16) : 0xFFFF0000u;
        }
    }

#pragma unroll
    for (int i = 0; i < 32; i++) planes[i] = keys[i];
    transpose32(planes);
    unsigned T2 = radix_rank16(planes, nv - kT - 1);
    unsigned T1 = 0;
    if (kT > 0) T1 = radix_rank16(planes, kT - 1);

    int c1 = 0, c2 = 0;
    float s1 = 0.f, s2 = 0.f;
#pragma unroll
    for (int i = 0; i < 32; i++) {
        unsigned kv = keys[i];
        float fv = keyToFloat16(kv);
        if (kT > 0 && kv < T1) { c1++; s1 += fv; }
        if (kv < T2) { c2++; s2 += fv; }
    }
    c1 = __reduce_add_sync(0xFFFFFFFFu, c1);
    c2 = __reduce_add_sync(0xFFFFFFFFu, c2);
#pragma unroll
    for (int o = 16; o; o >>= 1) {
        s1 += __shfl_xor_sync(0xFFFFFFFFu, s1, o);
        s2 += __shfl_xor_sync(0xFFFFFFFFu, s2, o);
    }
    float Sk = (kT > 0) ? (s1 + (float)(kT - c1) * keyToFloat16(T1)) : 0.f;
    float Snk = s2 + (float)((nv - kT) - c2) * keyToFloat16(T2);
    if (lane == 0) g_agg[warp] = (Snk - Sk) / (float)(nv - 2 * kT);
}

// ------------------------- decode MLP -------------------------
// grid (8 hblocks, 16 batch-groups), 128 threads; 4 batches per block.
__global__ void __launch_bounds__(128) decode1_kernel(const float* __restrict__ W3,
                                                      const float* __restrict__ b3) {
    __shared__ float sa[4][1024];
    int h = blockIdx.x * 128 + threadIdx.x;
    int bg = blockIdx.y * 4;
    for (int i = threadIdx.x; i < 4 * 1024; i += 128)
        sa[i >> 10][i & 1023] = g_agg[(bg + (i >> 10)) * 1024 + (i & 1023)];
    __syncthreads();
    float accv[4] = {0.f, 0.f, 0.f, 0.f};
    for (int k2 = 0; k2 < 1024; k2++) {
        float w = W3[(size_t)k2 * 1024 + h];
#pragma unroll
        for (int ii = 0; ii < 4; ii++) accv[ii] += sa[ii][k2] * w;
    }
    float bb = b3[h];
#pragma unroll
    for (int ii = 0; ii < 4; ii++) g_T[(bg + ii) * 1024 + h] = fmaxf(accv[ii] + bb, 0.f);
}

__global__ void decode2_kernel(const float* __restrict__ W4, const float* __restrict__ b4,
                               float* __restrict__ out) {
    int gw = blockIdx.x * 8 + (threadIdx.x >> 5);
    int lane = threadIdx.x & 31;
    if (gw >= 640) return;
    int b = gw / 10, o = gw - 10 * b;
    float acc = 0.f;
#pragma unroll
    for (int i = 0; i < 32; i++) {
        int kidx = i * 32 + lane;
        acc += g_T[b * 1024 + kidx] * W4[(size_t)kidx * 10 + o];
    }
#pragma unroll
    for (int oo = 16; oo; oo >>= 1) acc += __shfl_xor_sync(0xFFFFFFFFu, acc, oo);
    if (lane == 0) out[b * 10 + o] = acc + b4[o];
}

// ------------------------- launch -------------------------
extern "C" void kernel_launch(void* const* d_in, const int* in_sizes, int n_in,
                              void* d_out, int out_size) {
    const float* X = (const float*)d_in[0];
    const float* mask = (const float*)d_in[1];
    const float* W1 = (const float*)d_in[2];
    const float* b1 = (const float*)d_in[3];
    const float* W2 = (const float*)d_in[4];
    const float* b2 = (const float*)d_in[5];
    const float* W3 = (const float*)d_in[6];
    const float* b3 = (const float*)d_in[7];
    const float* W4 = (const float*)d_in[8];
    const float* b4 = (const float*)d_in[9];
    float* out = (float*)d_out;

    void *pXh, *pW1T, *pW2T, *pH1, *pET;
    cudaGetSymbolAddress(&pXh, g_Xh);
    cudaGetSymbolAddress(&pW1T, g_W1T);
    cudaGetSymbolAddress(&pW2T, g_W2T);
    cudaGetSymbolAddress(&pH1, g_H1);
    cudaGetSymbolAddress(&pET, g_ET);

    cudaFuncSetAttribute(gemm_fp16<true, false, 1>, cudaFuncAttributeMaxDynamicSharedMemorySize, GEMM_SMEM);
    cudaFuncSetAttribute(gemm_fp16<false, true, 2>, cudaFuncAttributeMaxDynamicSharedMemorySize, GEMM_SMEM);

    prep_kernel<<<PREP_TOTAL, 256>>>(X, mask, W1, W2);

    // GEMM1: H1[m,h] = relu(X[m,:]·W1T[h,:] + b1[h]); skip fully-invalid m-tiles
    gemm_fp16<true, false, 1><<<dim3(DH_ / BN, (B_ * N_) / BM, 1), 256, GEMM_SMEM>>>(
        (const __half*)pXh, (const __half*)pW1T, b1, (__half*)pH1,
        DIN_, DH_, 0, 0);

    // GEMM2 (transposed out): ET[b][h][n] = W2T[h,:]·H1[b][n,:] + b2[h]; skip invalid n-tiles
    gemm_fp16<false, true, 2><<<dim3(N_ / BN, DH_ / BM, B_), 256, GEMM_SMEM>>>(
        (const __half*)pW2T, (const __half*)pH1, b2, (__half*)pET,
        DH_, N_, (size_t)N_ * DH_, (size_t)DH_ * N_);

    select_kernel<<<(B_ * DH_) / 8, 256>>>();
    decode1_kernel<<<dim3(8, 16), 128>>>(W3, b3);
    decode2_kernel<<<80, 256>>>(W4, b4, out);
}

// round 10
// speedup vs baseline: 1.6023x; 1.0021x over previous
#include <cuda_runtime.h>
#include <cuda_fp16.h>
#include <cstdint>
#include <cstddef>

#define B_    64
#define N_    1024
#define DIN_  512
#define DH_   1024

#define BM 128
#define BN 128
#define BK 64
#define SSTRIDE 72           // fp16 elems per smem row: 64 data + 8 pad (144B)
#define TS 3
#define STAGE_HALFS ((BM + BN) * SSTRIDE)   // 18432 halfs = 36864 B
#define GEMM_SMEM (TS * STAGE_HALFS * 2)    // 110592 B

// prep kernel block partition
#define PREP_CAST_BLKS 32768
#define PREP_W1_BASE   PREP_CAST_BLKS
#define PREP_W1_BLKS   512
#define PREP_W2_BASE   (PREP_W1_BASE + PREP_W1_BLKS)
#define PREP_W2_BLKS   1024
#define PREP_NV_BASE   (PREP_W2_BASE + PREP_W2_BLKS)
#define PREP_NV_BLKS   64
#define PREP_TOTAL     (PREP_NV_BASE + PREP_NV_BLKS)

// ------------------------- static device scratch -------------------------
__device__ __half g_Xh[(size_t)B_ * N_ * DIN_];
__device__ __half g_W1T[(size_t)DH_ * DIN_];
__device__ __half g_W2T[(size_t)DH_ * DH_];
__device__ __half g_H1[(size_t)B_ * N_ * DH_];
__device__ __half g_ET[(size_t)B_ * DH_ * N_];
__device__ float  g_agg[B_ * DH_];
__device__ float  g_T[B_ * DH_];
__device__ int    g_nv[B_];
__device__ int    g_kk[B_];
__device__ unsigned g_bits[B_ * (N_ / 32)];

// ------------------------- helpers -------------------------
__device__ __forceinline__ float keyToFloat16(unsigned k32) {
    unsigned t = k32 >> 16;
    unsigned short b = (t & 0x8000u) ? (unsigned short)(t ^ 0x8000u)
                                     : (unsigned short)(~t & 0xFFFFu);
    return __half2float(__ushort_as_half(b));
}

__device__ __forceinline__ void mma16816(float* c, const uint32_t* a, uint32_t b0, uint32_t b1) {
    asm volatile(
        "mma.sync.aligned.m16n8k16.row.col.f32.f16.f16.f32 "
        "{%0,%1,%2,%3},{%4,%5,%6,%7},{%8,%9},{%0,%1,%2,%3};\n"
        : "+f"(c[0]), "+f"(c[1]), "+f"(c[2]), "+f"(c[3])
        : "r"(a[0]), "r"(a[1]), "r"(a[2]), "r"(a[3]), "r"(b0), "r"(b1));
}
__device__ __forceinline__ void ldmat4(uint32_t* r, uint32_t addr) {
    asm volatile("ldmatrix.sync.aligned.m8n8.x4.shared.b16 {%0,%1,%2,%3},[%4];\n"
                 : "=r"(r[0]), "=r"(r[1]), "=r"(r[2]), "=r"(r[3])
                 : "r"(addr));
}
#define CP16(dst, src) asm volatile("cp.async.cg.shared.global [%0],[%1],16;\n" ::"r"(dst), "l"(src))

// Half bit-transpose: 32 keys of 16 significant bits (bits 31..16) -> 16 planes.
// Stage J=16 degenerates (low halves are zero): planes[k] = keys[k] | keys[k+16]>>16.
// Words 16..31 would be zero and never feed words 0..15 in later stages, so
// stages J=8,4,2,1 run on 16 words only. planes[j] (j=0..15) equals the full
// transpose's planes[j] = bit-plane of key bit (31-j).
template <int J>
__device__ __forceinline__ void tstep16(unsigned* A, unsigned m) {
#pragma unroll
    for (int k0 = 0; k0 < 8; k0++) {
        int k = ((k0 & ~(J - 1)) << 1) | (k0 & (J - 1));
        unsigned t = (A[k] ^ (A[k + J] >> J)) & m;
        A[k] ^= t;
        A[k + J] ^= (t << J);
    }
}
__device__ __forceinline__ void half_transpose(const unsigned* keys, unsigned* planes) {
#pragma unroll
    for (int k = 0; k < 16; k++) planes[k] = keys[k] | (keys[k + 16] >> 16);
    tstep16<8>(planes, 0x00FF00FFu);
    tstep16<4>(planes, 0x0F0F0F0Fu);
    tstep16<2>(planes, 0x33333333u);
    tstep16<1>(planes, 0x55555555u);
}

// Fused dual radix descent: find the keys at ranks r1 and r2 (r1 <= r2) over
// the warp's 1024 keys in one pass. Counts packed into one REDUX per bit.
__device__ __forceinline__ void radix_rank16_dual(const unsigned* planes, int r1, int r2,
                                                  unsigned& T1, unsigned& T2) {
    unsigned C1 = 0xFFFFFFFFu, C2 = 0xFFFFFFFFu, p1 = 0u, p2 = 0u;
#pragma unroll
    for (int bit = 31; bit >= 16; --bit) {
        unsigned P = planes[31 - bit];
        unsigned z1 = C1 & ~P;
        unsigned z2 = C2 & ~P;
        unsigned packed = (unsigned)__popc(z1) | ((unsigned)__popc(z2) << 16);
        unsigned tot = __reduce_add_sync(0xFFFFFFFFu, packed);
        int c1 = (int)(tot & 0xFFFFu), c2 = (int)(tot >> 16);
        if (r1 < c1) { C1 = z1; } else { r1 -= c1; C1 &= P; p1 |= (1u << bit); }
        if (r2 < c2) { C2 = z2; } else { r2 -= c2; C2 &= P; p2 |= (1u << bit); }
    }
    T1 = p1;
    T2 = p2;
}

// ------------------------- fused prep kernel -------------------------
__global__ void __launch_bounds__(256) prep_kernel(
    const float* __restrict__ X, const float* __restrict__ mask,
    const float* __restrict__ W1, const float* __restrict__ W2) {
    __shared__ float tile[32][33];
    const int bid = blockIdx.x;
    const int tid = threadIdx.x;

    if (bid < PREP_CAST_BLKS) {
        int i = bid * 256 + tid;       // float4 index
        int row = i >> 7;              // 128 float4 per row
        if (mask[row] > 0.0f) {
            float4 v = ((const float4*)X)[i];
            __half2* p = (__half2*)&g_Xh[4 * (size_t)i];
            p[0] = __floats2half2_rn(v.x, v.y);
            p[1] = __floats2half2_rn(v.z, v.w);
        }
        return;
    }

    if (bid < PREP_NV_BASE) {
        const float* W;
        __half* WT;
        int Krows, local;
        if (bid < PREP_W2_BASE) {
            local = bid - PREP_W1_BASE;
            W = W1;
            Krows = DIN_;
            WT = g_W1T;
        } else {
            local = bid - PREP_W2_BASE;
            W = W2;
            Krows = DH_;
            WT = g_W2T;
        }
        int bx = local & 31, by = local >> 5;
        int tx = tid & 31, ty = tid >> 5;
#pragma unroll
        for (int i = 0; i < 32; i += 8) {
            int y = by * 32 + ty + i;
            tile[ty + i][tx] = W[(size_t)y * DH_ + bx * 32 + tx];
        }
        __syncthreads();
        int xo = by * 32 + tx;
#pragma unroll
        for (int i = 0; i < 32; i += 8) {
            int yo = bx * 32 + ty + i;
            WT[(size_t)yo * Krows + xo] = __float2half_rn(tile[tx][ty + i]);
        }
        return;
    }

    {
        int b = bid - PREP_NV_BASE;
        __shared__ int cnt;
        if (tid == 0) cnt = 0;
        __syncthreads();
        int lane = tid & 31, w = tid >> 5;
        int local = 0;
#pragma unroll
        for (int j = 0; j < 4; j++) {
            int widx = w + 8 * j;
            int n = widx * 32 + lane;
            int v = mask[(size_t)b * N_ + n] > 0.0f;
            unsigned word = __ballot_sync(0xFFFFFFFFu, v);
            if (lane == 0) {
                g_bits[b * 32 + widx] = word;
                local += __popc(word);
            }
        }
        if (lane == 0 && local) atomicAdd(&cnt, local);
        __syncthreads();
        if (tid == 0) {
            g_nv[b] = cnt;
            g_kk[b] = (int)((float)cnt * 0.1f);
        }
    }
}

// ------------------------- main GEMM (fp16 MMA, fp32 accum) -------------
template <bool RELU, bool BIAS_BY_ROW, int SKIP_MODE>
__global__ void __launch_bounds__(256, 2) gemm_fp16(
    const __half* __restrict__ A, const __half* __restrict__ B,
    const float* __restrict__ bias, __half* __restrict__ out,
    int K, int N, size_t zB, size_t zC) {
    extern __shared__ __half sm[];

    const int mBase = blockIdx.y * BM, nBase = blockIdx.x * BN;
    if (SKIP_MODE == 1) {
        if ((mBase & (N_ - 1)) >= g_nv[mBase >> 10]) return;
    } else if (SKIP_MODE == 2) {
        if (nBase >= g_nv[blockIdx.z]) return;
    }

    B += (size_t)blockIdx.z * zB;
    out += (size_t)blockIdx.z * zC;

    const int tid = threadIdx.x;
    const int lane = tid & 31;
    const int wid = tid >> 5;
    const int wm = (wid >> 2) * 64;
    const int wn = (wid & 3) * 32;
    const int gq = lane >> 2, tg = lane & 3;
    const int KT = K / BK;

    float acc[4][4][4];
#pragma unroll
    for (int a = 0; a < 4; a++)
#pragma unroll
        for (int b = 0; b < 4; b++)
#pragma unroll
            for (int c = 0; c < 4; c++) acc[a][b][c] = 0.f;

    auto load = [&](int kt, int s) {
        __half* sa = sm + s * STAGE_HALFS;
        int k0 = kt * BK;
#pragma unroll
        for (int p = 0; p < 8; p++) {
            int v = tid + 256 * p;
            int row = v >> 3;
            int cv = (v & 7) * 8;
            uint32_t d = (uint32_t)__cvta_generic_to_shared(sa + row * SSTRIDE + cv);
            const __half* src = (row < BM) ? (A + (size_t)(mBase + row) * K + k0 + cv)
                                           : (B + (size_t)(nBase + row - BM) * K + k0 + cv);
            CP16(d, src);
        }
        asm volatile("cp.async.commit_group;\n");
    };

    load(0, 0);
    if (KT > 1) load(1, 1);
    for (int kt = 0; kt < KT; kt++) {
        int s = kt % TS;
        if (kt + 1 < KT) {
            asm volatile("cp.async.wait_group 1;\n");
        } else {
            asm volatile("cp.async.wait_group 0;\n");
        }
        __syncthreads();
        if (kt + 2 < KT) load(kt + 2, (kt + 2) % TS);

        const __half* sa = sm + s * STAGE_HALFS;
        const __half* sb = sa + BM * SSTRIDE;
#pragma unroll
        for (int kk = 0; kk < BK; kk += 16) {
            uint32_t af[4][4];
#pragma unroll
            for (int mi = 0; mi < 4; mi++) {
                uint32_t ad = (uint32_t)__cvta_generic_to_shared(
                    sa + (wm + mi * 16 + (lane & 15)) * SSTRIDE + kk + (lane >> 4) * 8);
                ldmat4(af[mi], ad);
            }
#pragma unroll
            for (int ni = 0; ni < 4; ni++) {
                const __half* bp = sb + (wn + ni * 8 + gq) * SSTRIDE + kk + 2 * tg;
                uint32_t b0 = *(const uint32_t*)bp;
                uint32_t b1v = *(const uint32_t*)(bp + 8);
#pragma unroll
                for (int mi = 0; mi < 4; mi++) mma16816(acc[mi][ni], af[mi], b0, b1v);
            }
        }
    }

#pragma unroll
    for (int mi = 0; mi < 4; mi++) {
        int r0 = mBase + wm + mi * 16 + gq;
        float bvR0 = 0.f, bvR1 = 0.f;
        if (BIAS_BY_ROW) { bvR0 = bias[r0]; bvR1 = bias[r0 + 8]; }
#pragma unroll
        for (int ni = 0; ni < 4; ni++) {
            int col = nBase + wn + ni * 8 + 2 * tg;
            float v00, v01, v10, v11;
            if (BIAS_BY_ROW) {
                v00 = acc[mi][ni][0] + bvR0; v01 = acc[mi][ni][1] + bvR0;
                v10 = acc[mi][ni][2] + bvR1; v11 = acc[mi][ni][3] + bvR1;
            } else {
                float bv0 = bias[col], bv1 = bias[col + 1];
                v00 = acc[mi][ni][0] + bv0; v01 = acc[mi][ni][1] + bv1;
                v10 = acc[mi][ni][2] + bv0; v11 = acc[mi][ni][3] + bv1;
            }
            if (RELU) {
                v00 = fmaxf(v00, 0.f); v01 = fmaxf(v01, 0.f);
                v10 = fmaxf(v10, 0.f); v11 = fmaxf(v11, 0.f);
            }
            *(__half2*)(out + (size_t)r0 * N + col) = __floats2half2_rn(v00, v01);
            *(__half2*)(out + (size_t)(r0 + 8) * N + col) = __floats2half2_rn(v10, v11);
        }
    }
}

// ------------------------- trimmed-mean select -------------------------
// nv >= N/2 = 512 guaranteed => kT = floor(nv*0.1) >= 51 > 0 always.
__global__ void __launch_bounds__(256) select_kernel() {
    int warp = (blockIdx.x << 3) + (threadIdx.x >> 5);  // b*1024 + h
    int lane = threadIdx.x & 31;
    int b = warp >> 10;
    const __half* col = g_ET + ((size_t)warp << 10);

    int nv = g_nv[b], kT = g_kk[b];

    unsigned keys[32];
#pragma unroll
    for (int j = 0; j < 4; j++) {
        int n0 = j * 256 + lane * 8;
        if (j * 256 >= nv) {
#pragma unroll
            for (int i = 0; i < 8; i++) keys[j * 8 + i] = 0xFFFF0000u;
            continue;
        }
        uint4 v = *(const uint4*)(col + n0);
        unsigned wb = g_bits[(b << 5) + (n0 >> 5)] >> ((lane & 3) * 8);
        unsigned ws[4] = {v.x, v.y, v.z, v.w};
#pragma unroll
        for (int i = 0; i < 8; i++) {
            unsigned h = (ws[i >> 1] >> ((i & 1) * 16)) & 0xFFFFu;
            unsigned k16 = (h & 0x8000u) ? (~h & 0xFFFFu) : (h | 0x8000u);
            keys[j * 8 + i] = ((wb >> i) & 1u) ? (k16 << 16) : 0xFFFF0000u;
        }
    }

    unsigned planes[16];
    half_transpose(keys, planes);

    unsigned T1, T2;
    radix_rank16_dual(planes, kT - 1, nv - kT - 1, T1, T2);

    int c1 = 0, c2 = 0;
    float s1 = 0.f, s2 = 0.f;
#pragma unroll
    for (int i = 0; i < 32; i++) {
        unsigned kv = keys[i];
        float fv = keyToFloat16(kv);
        if (kv < T1) { c1++; s1 += fv; }
        if (kv < T2) { c2++; s2 += fv; }
    }
    unsigned ctot = __reduce_add_sync(0xFFFFFFFFu, (unsigned)c1 | ((unsigned)c2 << 16));
    c1 = (int)(ctot & 0xFFFFu);
    c2 = (int)(ctot >> 16);
#pragma unroll
    for (int o = 16; o; o >>= 1) {
        s1 += __shfl_xor_sync(0xFFFFFFFFu, s1, o);
        s2 += __shfl_xor_sync(0xFFFFFFFFu, s2, o);
    }
    float Sk = s1 + (float)(kT - c1) * keyToFloat16(T1);
    float Snk = s2 + (float)((nv - kT) - c2) * keyToFloat16(T2);
    if (lane == 0) g_agg[warp] = (Snk - Sk) / (float)(nv - 2 * kT);
}

// ------------------------- decode MLP -------------------------
__global__ void __launch_bounds__(128) decode1_kernel(const float* __restrict__ W3,
                                                      const float* __restrict__ b3) {
    __shared__ float sa[4][1024];
    int h = blockIdx.x * 128 + threadIdx.x;
    int bg = blockIdx.y * 4;
    for (int i = threadIdx.x; i < 4 * 1024; i += 128)
        sa[i >> 10][i & 1023] = g_agg[(bg + (i >> 10)) * 1024 + (i & 1023)];
    __syncthreads();
    float accv[4] = {0.f, 0.f, 0.f, 0.f};
    for (int k2 = 0; k2 < 1024; k2++) {
        float w = W3[(size_t)k2 * 1024 + h];
#pragma unroll
        for (int ii = 0; ii < 4; ii++) accv[ii] += sa[ii][k2] * w;
    }
    float bb = b3[h];
#pragma unroll
    for (int ii = 0; ii < 4; ii++) g_T[(bg + ii) * 1024 + h] = fmaxf(accv[ii] + bb, 0.f);
}

__global__ void decode2_kernel(const float* __restrict__ W4, const float* __restrict__ b4,
                               float* __restrict__ out) {
    int gw = blockIdx.x * 8 + (threadIdx.x >> 5);
    int lane = threadIdx.x & 31;
    if (gw >= 640) return;
    int b = gw / 10, o = gw - 10 * b;
    float acc = 0.f;
#pragma unroll
    for (int i = 0; i < 32; i++) {
        int kidx = i * 32 + lane;
        acc += g_T[b * 1024 + kidx] * W4[(size_t)kidx * 10 + o];
    }
#pragma unroll
    for (int oo = 16; oo; oo >>= 1) acc += __shfl_xor_sync(0xFFFFFFFFu, acc, oo);
    if (lane == 0) out[b * 10 + o] = acc + b4[o];
}

// ------------------------- launch -------------------------
extern "C" void kernel_launch(void* const* d_in, const int* in_sizes, int n_in,
                              void* d_out, int out_size) {
    const float* X = (const float*)d_in[0];
    const float* mask = (const float*)d_in[1];
    const float* W1 = (const float*)d_in[2];
    const float* b1 = (const float*)d_in[3];
    const float* W2 = (const float*)d_in[4];
    const float* b2 = (const float*)d_in[5];
    const float* W3 = (const float*)d_in[6];
    const float* b3 = (const float*)d_in[7];
    const float* W4 = (const float*)d_in[8];
    const float* b4 = (const float*)d_in[9];
    float* out = (float*)d_out;

    void *pXh, *pW1T, *pW2T, *pH1, *pET;
    cudaGetSymbolAddress(&pXh, g_Xh);
    cudaGetSymbolAddress(&pW1T, g_W1T);
    cudaGetSymbolAddress(&pW2T, g_W2T);
    cudaGetSymbolAddress(&pH1, g_H1);
    cudaGetSymbolAddress(&pET, g_ET);

    cudaFuncSetAttribute(gemm_fp16<true, false, 1>, cudaFuncAttributeMaxDynamicSharedMemorySize, GEMM_SMEM);
    cudaFuncSetAttribute(gemm_fp16<false, true, 2>, cudaFuncAttributeMaxDynamicSharedMemorySize, GEMM_SMEM);

    prep_kernel<<<PREP_TOTAL, 256>>>(X, mask, W1, W2);

    gemm_fp16<true, false, 1><<<dim3(DH_ / BN, (B_ * N_) / BM, 1), 256, GEMM_SMEM>>>(
        (const __half*)pXh, (const __half*)pW1T, b1, (__half*)pH1,
        DIN_, DH_, 0, 0);

    gemm_fp16<false, true, 2><<<dim3(N_ / BN, DH_ / BM, B_), 256, GEMM_SMEM>>>(
        (const __half*)pW2T, (const __half*)pH1, b2, (__half*)pET,
        DH_, N_, (size_t)N_ * DH_, (size_t)DH_ * N_);

    select_kernel<<<(B_ * DH_) / 8, 256>>>();
    decode1_kernel<<<dim3(8, 16), 128>>>(W3, b3);
    decode2_kernel<<<80, 256>>>(W4, b4, out);
}

// round 11
// speedup vs baseline: 1.6601x; 1.0360x over previous
#include <cuda_runtime.h>
#include <cuda_fp16.h>
#include <cstdint>
#include <cstddef>

#define B_    64
#define N_    1024
#define DIN_  512
#define DH_   1024

#define BM 128
#define BN 128
#define BK 64
#define SSTRIDE 72           // fp16 elems per smem row: 64 data + 8 pad (144B)
#define TS 3
#define STAGE_HALFS ((BM + BN) * SSTRIDE)   // 18432 halfs = 36864 B
#define GEMM_SMEM (TS * STAGE_HALFS * 2)    // 110592 B

// prep kernel block partition
#define PREP_CAST_BLKS 32768
#define PREP_W1_BASE   PREP_CAST_BLKS
#define PREP_W1_BLKS   512
#define PREP_W2_BASE   (PREP_W1_BASE + PREP_W1_BLKS)
#define PREP_W2_BLKS   1024
#define PREP_NV_BASE   (PREP_W2_BASE + PREP_W2_BLKS)
#define PREP_NV_BLKS   64
#define PREP_TOTAL     (PREP_NV_BASE + PREP_NV_BLKS)

// ------------------------- static device scratch -------------------------
__device__ __half g_Xh[(size_t)B_ * N_ * DIN_];
__device__ __half g_W1T[(size_t)DH_ * DIN_];
__device__ __half g_W2T[(size_t)DH_ * DH_];
__device__ __half g_H1[(size_t)B_ * N_ * DH_];
__device__ __half g_ET[(size_t)B_ * DH_ * N_];
__device__ float  g_agg[B_ * DH_];
__device__ float  g_T[B_ * DH_];
__device__ int    g_nv[B_];
__device__ int    g_kk[B_];
__device__ unsigned g_bits[B_ * (N_ / 32)];

// ------------------------- helpers -------------------------
__device__ __forceinline__ float keyToFloat16(unsigned k32) {
    unsigned t = k32 >> 16;
    unsigned short b = (t & 0x8000u) ? (unsigned short)(t ^ 0x8000u)
                                     : (unsigned short)(~t & 0xFFFFu);
    return __half2float(__ushort_as_half(b));
}

__device__ __forceinline__ void mma16816(float* c, const uint32_t* a, uint32_t b0, uint32_t b1) {
    asm volatile(
        "mma.sync.aligned.m16n8k16.row.col.f32.f16.f16.f32 "
        "{%0,%1,%2,%3},{%4,%5,%6,%7},{%8,%9},{%0,%1,%2,%3};\n"
        : "+f"(c[0]), "+f"(c[1]), "+f"(c[2]), "+f"(c[3])
        : "r"(a[0]), "r"(a[1]), "r"(a[2]), "r"(a[3]), "r"(b0), "r"(b1));
}
__device__ __forceinline__ void ldmat4(uint32_t* r, uint32_t addr) {
    asm volatile("ldmatrix.sync.aligned.m8n8.x4.shared.b16 {%0,%1,%2,%3},[%4];\n"
                 : "=r"(r[0]), "=r"(r[1]), "=r"(r[2]), "=r"(r[3])
                 : "r"(addr));
}
#define CP16(dst, src) asm volatile("cp.async.cg.shared.global [%0],[%1],16;\n" ::"r"(dst), "l"(src))

// Half bit-transpose on packed keys. pk[m] holds two 16-bit keys: slot m in
// bits 31:16, slot m+16 in bits 15:0 — exactly the state after the (now free)
// first combine stage. Stages J=8,4,2,1 complete the 32x32 transpose restricted
// to the 16 meaningful output words: planes[j] = bit-plane of key bit (31-j).
template <int J>
__device__ __forceinline__ void tstep16(unsigned* A, unsigned m) {
#pragma unroll
    for (int k0 = 0; k0 < 8; k0++) {
        int k = ((k0 & ~(J - 1)) << 1) | (k0 & (J - 1));
        unsigned t = (A[k] ^ (A[k + J] >> J)) & m;
        A[k] ^= t;
        A[k + J] ^= (t << J);
    }
}
__device__ __forceinline__ void half_transpose_packed(unsigned* planes) {
    tstep16<8>(planes, 0x00FF00FFu);
    tstep16<4>(planes, 0x0F0F0F0Fu);
    tstep16<2>(planes, 0x33333333u);
    tstep16<1>(planes, 0x55555555u);
}

// Fused dual radix descent: keys at ranks r1 <= r2 over the warp's 1024 keys.
// Also returns residual ranks r1f/r2f = rank within the equal-key set, from
// which count_lt(Ti) = ri_init - rif (used for exact tie correction).
__device__ __forceinline__ void radix_dual(const unsigned* planes, int r1, int r2,
                                           unsigned& T1, unsigned& T2, int& r1f, int& r2f) {
    unsigned C1 = 0xFFFFFFFFu, C2 = 0xFFFFFFFFu, p1 = 0u, p2 = 0u;
#pragma unroll
    for (int bit = 31; bit >= 16; --bit) {
        unsigned P = planes[31 - bit];
        unsigned z1 = C1 & ~P;
        unsigned z2 = C2 & ~P;
        unsigned tot = __reduce_add_sync(0xFFFFFFFFu,
                                         (unsigned)__popc(z1) + ((unsigned)__popc(z2) << 16));
        int c1 = (int)(tot & 0xFFFFu), c2 = (int)(tot >> 16);
        if (r1 < c1) { C1 = z1; } else { r1 -= c1; C1 &= P; p1 |= (1u << bit); }
        if (r2 < c2) { C2 = z2; } else { r2 -= c2; C2 &= P; p2 |= (1u << bit); }
    }
    T1 = p1; T2 = p2; r1f = r1; r2f = r2;
}

// ------------------------- fused prep kernel -------------------------
__global__ void __launch_bounds__(256) prep_kernel(
    const float* __restrict__ X, const float* __restrict__ mask,
    const float* __restrict__ W1, const float* __restrict__ W2) {
    __shared__ float tile[32][33];
    const int bid = blockIdx.x;
    const int tid = threadIdx.x;

    if (bid < PREP_CAST_BLKS) {
        int i = bid * 256 + tid;       // float4 index
        int row = i >> 7;              // 128 float4 per row
        if (mask[row] > 0.0f) {
            float4 v = ((const float4*)X)[i];
            __half2* p = (__half2*)&g_Xh[4 * (size_t)i];
            p[0] = __floats2half2_rn(v.x, v.y);
            p[1] = __floats2half2_rn(v.z, v.w);
        }
        return;
    }

    if (bid < PREP_NV_BASE) {
        const float* W;
        __half* WT;
        int Krows, local;
        if (bid < PREP_W2_BASE) {
            local = bid - PREP_W1_BASE;
            W = W1;
            Krows = DIN_;
            WT = g_W1T;
        } else {
            local = bid - PREP_W2_BASE;
            W = W2;
            Krows = DH_;
            WT = g_W2T;
        }
        int bx = local & 31, by = local >> 5;
        int tx = tid & 31, ty = tid >> 5;
#pragma unroll
        for (int i = 0; i < 32; i += 8) {
            int y = by * 32 + ty + i;
            tile[ty + i][tx] = W[(size_t)y * DH_ + bx * 32 + tx];
        }
        __syncthreads();
        int xo = by * 32 + tx;
#pragma unroll
        for (int i = 0; i < 32; i += 8) {
            int yo = bx * 32 + ty + i;
            WT[(size_t)yo * Krows + xo] = __float2half_rn(tile[tx][ty + i]);
        }
        return;
    }

    {
        int b = bid - PREP_NV_BASE;
        __shared__ int cnt;
        if (tid == 0) cnt = 0;
        __syncthreads();
        int lane = tid & 31, w = tid >> 5;
        int local = 0;
#pragma unroll
        for (int j = 0; j < 4; j++) {
            int widx = w + 8 * j;
            int n = widx * 32 + lane;
            int v = mask[(size_t)b * N_ + n] > 0.0f;
            unsigned word = __ballot_sync(0xFFFFFFFFu, v);
            if (lane == 0) {
                g_bits[b * 32 + widx] = word;
                local += __popc(word);
            }
        }
        if (lane == 0 && local) atomicAdd(&cnt, local);
        __syncthreads();
        if (tid == 0) {
            g_nv[b] = cnt;
            g_kk[b] = (int)((float)cnt * 0.1f);
        }
    }
}

// ------------------------- main GEMM (fp16 MMA, fp32 accum) -------------
template <bool RELU, bool BIAS_BY_ROW, int SKIP_MODE>
__global__ void __launch_bounds__(256, 2) gemm_fp16(
    const __half* __restrict__ A, const __half* __restrict__ B,
    const float* __restrict__ bias, __half* __restrict__ out,
    int K, int N, size_t zB, size_t zC) {
    extern __shared__ __half sm[];

    const int mBase = blockIdx.y * BM, nBase = blockIdx.x * BN;
    if (SKIP_MODE == 1) {
        if ((mBase & (N_ - 1)) >= g_nv[mBase >> 10]) return;
    } else if (SKIP_MODE == 2) {
        if (nBase >= g_nv[blockIdx.z]) return;
    }

    B += (size_t)blockIdx.z * zB;
    out += (size_t)blockIdx.z * zC;

    const int tid = threadIdx.x;
    const int lane = tid & 31;
    const int wid = tid >> 5;
    const int wm = (wid >> 2) * 64;
    const int wn = (wid & 3) * 32;
    const int gq = lane >> 2, tg = lane & 3;
    const int KT = K / BK;

    float acc[4][4][4];
#pragma unroll
    for (int a = 0; a < 4; a++)
#pragma unroll
        for (int b = 0; b < 4; b++)
#pragma unroll
            for (int c = 0; c < 4; c++) acc[a][b][c] = 0.f;

    auto load = [&](int kt, int s) {
        __half* sa = sm + s * STAGE_HALFS;
        int k0 = kt * BK;
#pragma unroll
        for (int p = 0; p < 8; p++) {
            int v = tid + 256 * p;
            int row = v >> 3;
            int cv = (v & 7) * 8;
            uint32_t d = (uint32_t)__cvta_generic_to_shared(sa + row * SSTRIDE + cv);
            const __half* src = (row < BM) ? (A + (size_t)(mBase + row) * K + k0 + cv)
                                           : (B + (size_t)(nBase + row - BM) * K + k0 + cv);
            CP16(d, src);
        }
        asm volatile("cp.async.commit_group;\n");
    };

    load(0, 0);
    if (KT > 1) load(1, 1);
    for (int kt = 0; kt < KT; kt++) {
        int s = kt % TS;
        if (kt + 1 < KT) {
            asm volatile("cp.async.wait_group 1;\n");
        } else {
            asm volatile("cp.async.wait_group 0;\n");
        }
        __syncthreads();
        if (kt + 2 < KT) load(kt + 2, (kt + 2) % TS);

        const __half* sa = sm + s * STAGE_HALFS;
        const __half* sb = sa + BM * SSTRIDE;
#pragma unroll
        for (int kk = 0; kk < BK; kk += 16) {
            uint32_t af[4][4];
#pragma unroll
            for (int mi = 0; mi < 4; mi++) {
                uint32_t ad = (uint32_t)__cvta_generic_to_shared(
                    sa + (wm + mi * 16 + (lane & 15)) * SSTRIDE + kk + (lane >> 4) * 8);
                ldmat4(af[mi], ad);
            }
#pragma unroll
            for (int ni = 0; ni < 4; ni++) {
                const __half* bp = sb + (wn + ni * 8 + gq) * SSTRIDE + kk + 2 * tg;
                uint32_t b0 = *(const uint32_t*)bp;
                uint32_t b1v = *(const uint32_t*)(bp + 8);
#pragma unroll
                for (int mi = 0; mi < 4; mi++) mma16816(acc[mi][ni], af[mi], b0, b1v);
            }
        }
    }

#pragma unroll
    for (int mi = 0; mi < 4; mi++) {
        int r0 = mBase + wm + mi * 16 + gq;
        float bvR0 = 0.f, bvR1 = 0.f;
        if (BIAS_BY_ROW) { bvR0 = bias[r0]; bvR1 = bias[r0 + 8]; }
#pragma unroll
        for (int ni = 0; ni < 4; ni++) {
            int col = nBase + wn + ni * 8 + 2 * tg;
            float v00, v01, v10, v11;
            if (BIAS_BY_ROW) {
                v00 = acc[mi][ni][0] + bvR0; v01 = acc[mi][ni][1] + bvR0;
                v10 = acc[mi][ni][2] + bvR1; v11 = acc[mi][ni][3] + bvR1;
            } else {
                float bv0 = bias[col], bv1 = bias[col + 1];
                v00 = acc[mi][ni][0] + bv0; v01 = acc[mi][ni][1] + bv1;
                v10 = acc[mi][ni][2] + bv0; v11 = acc[mi][ni][3] + bv1;
            }
            if (RELU) {
                v00 = fmaxf(v00, 0.f); v01 = fmaxf(v01, 0.f);
                v10 = fmaxf(v10, 0.f); v11 = fmaxf(v11, 0.f);
            }
            *(__half2*)(out + (size_t)r0 * N + col) = __floats2half2_rn(v00, v01);
            *(__half2*)(out + (size_t)(r0 + 8) * N + col) = __floats2half2_rn(v10, v11);
        }
    }
}

// ------------------------- trimmed-mean select -------------------------
// Prefix mask: valid <=> n < nv (nv >= 512 => kT >= 51 > 0 always).
// Keys kept packed: pk[m] = key(slot m) in bits 31:16, key(slot m+16) in 15:0,
// where slot m = element n0+2i+1 (high half2 lane), slot m+16 = element n0+2i.
__global__ void __launch_bounds__(256) select_kernel() {
    int warp = (blockIdx.x << 3) + (threadIdx.x >> 5);  // b*1024 + h
    int lane = threadIdx.x & 31;
    int b = warp >> 10;
    const __half* col = g_ET + ((size_t)warp << 10);

    int nv = g_nv[b], kT = g_kk[b];

    unsigned pk[16];
#pragma unroll
    for (int j = 0; j < 4; j++) {
        int n0 = j * 256 + lane * 8;
        if (j * 256 >= nv) {  // whole chunk beyond valid prefix
#pragma unroll
            for (int i = 0; i < 4; i++) pk[j * 4 + i] = 0xFFFFFFFFu;
            continue;
        }
        uint4 v = *(const uint4*)(col + n0);
        unsigned ws[4] = {v.x, v.y, v.z, v.w};
#pragma unroll
        for (int i = 0; i < 4; i++) {
            unsigned hh = ws[i];
            unsigned t = hh & 0x80008000u;
            unsigned m = (t >> 15) * 0x7FFFu;
            pk[j * 4 + i] = hh ^ (m | 0x80008000u);  // monotone fp16->u16, SIMD
        }
        int rr = nv - n0;  // valid count among this lane's 8
        if (rr < 8) {      // rare boundary fixup: invalid lanes -> 0xFFFF
#pragma unroll
            for (int i = 0; i < 4; i++) {
                unsigned fix = ((2 * i >= rr) ? 0x0000FFFFu : 0u)
                             | ((2 * i + 1 >= rr) ? 0xFFFF0000u : 0u);
                pk[j * 4 + i] |= fix;
            }
        }
    }

    unsigned planes[16];
#pragma unroll
    for (int i = 0; i < 16; i++) planes[i] = pk[i];
    half_transpose_packed(planes);

    unsigned T1, T2;
    int r1f, r2f;
    radix_dual(planes, kT - 1, nv - kT - 1, T1, T2, r1f, r2f);
    const unsigned D = T2 - T1;

    // band sum: sum of values with T1 <= key < T2 (unsigned range test)
    float s = 0.f;
#pragma unroll
    for (int m = 0; m < 16; m++) {
        unsigned pkm = pk[m];
        unsigned t2 = (~pkm) & 0x80008000u;
        unsigned m2 = (t2 >> 15) * 0x7FFFu;
        unsigned ob = pkm ^ (m2 | 0x80008000u);  // inverse map, SIMD
        float2 f = __half22float2(*reinterpret_cast<__half2*>(&ob));
        unsigned kvh = pkm & 0xFFFF0000u;
        unsigned kvl = pkm << 16;
        if (kvh - T1 < D) s += f.y;
        if (kvl - T1 < D) s += f.x;
    }
#pragma unroll
    for (int o = 16; o; o >>= 1) s += __shfl_xor_sync(0xFFFFFFFFu, s, o);

    if (lane == 0) {
        float v1 = keyToFloat16(T1), v2 = keyToFloat16(T2);
        g_agg[warp] = (s + (float)(r2f + 1) * v2 - (float)(r1f + 1) * v1)
                      / (float)(nv - 2 * kT);
    }
}

// ------------------------- decode MLP -------------------------
__global__ void __launch_bounds__(128) decode1_kernel(const float* __restrict__ W3,
                                                      const float* __restrict__ b3) {
    __shared__ float sa[4][1024];
    int h = blockIdx.x * 128 + threadIdx.x;
    int bg = blockIdx.y * 4;
    for (int i = threadIdx.x; i < 4 * 1024; i += 128)
        sa[i >> 10][i & 1023] = g_agg[(bg + (i >> 10)) * 1024 + (i & 1023)];
    __syncthreads();
    float accv[4] = {0.f, 0.f, 0.f, 0.f};
    for (int k2 = 0; k2 < 1024; k2++) {
        float w = W3[(size_t)k2 * 1024 + h];
#pragma unroll
        for (int ii = 0; ii < 4; ii++) accv[ii] += sa[ii][k2] * w;
    }
    float bb = b3[h];
#pragma unroll
    for (int ii = 0; ii < 4; ii++) g_T[(bg + ii) * 1024 + h] = fmaxf(accv[ii] + bb, 0.f);
}

__global__ void decode2_kernel(const float* __restrict__ W4, const float* __restrict__ b4,
                               float* __restrict__ out) {
    int gw = blockIdx.x * 8 + (threadIdx.x >> 5);
    int lane = threadIdx.x & 31;
    if (gw >= 640) return;
    int b = gw / 10, o = gw - 10 * b;
    float acc = 0.f;
#pragma unroll
    for (int i = 0; i < 32; i++) {
        int kidx = i * 32 + lane;
        acc += g_T[b * 1024 + kidx] * W4[(size_t)kidx * 10 + o];
    }
#pragma unroll
    for (int oo = 16; oo; oo >>= 1) acc += __shfl_xor_sync(0xFFFFFFFFu, acc, oo);
    if (lane == 0) out[b * 10 + o] = acc + b4[o];
}

// ------------------------- launch -------------------------
extern "C" void kernel_launch(void* const* d_in, const int* in_sizes, int n_in,
                              void* d_out, int out_size) {
    const float* X = (const float*)d_in[0];
    const float* mask = (const float*)d_in[1];
    const float* W1 = (const float*)d_in[2];
    const float* b1 = (const float*)d_in[3];
    const float* W2 = (const float*)d_in[4];
    const float* b2 = (const float*)d_in[5];
    const float* W3 = (const float*)d_in[6];
    const float* b3 = (const float*)d_in[7];
    const float* W4 = (const float*)d_in[8];
    const float* b4 = (const float*)d_in[9];
    float* out = (float*)d_out;

    void *pXh, *pW1T, *pW2T, *pH1, *pET;
    cudaGetSymbolAddress(&pXh, g_Xh);
    cudaGetSymbolAddress(&pW1T, g_W1T);
    cudaGetSymbolAddress(&pW2T, g_W2T);
    cudaGetSymbolAddress(&pH1, g_H1);
    cudaGetSymbolAddress(&pET, g_ET);

    cudaFuncSetAttribute(gemm_fp16<true, false, 1>, cudaFuncAttributeMaxDynamicSharedMemorySize, GEMM_SMEM);
    cudaFuncSetAttribute(gemm_fp16<false, true, 2>, cudaFuncAttributeMaxDynamicSharedMemorySize, GEMM_SMEM);

    prep_kernel<<<PREP_TOTAL, 256>>>(X, mask, W1, W2);

    gemm_fp16<true, false, 1><<<dim3(DH_ / BN, (B_ * N_) / BM, 1), 256, GEMM_SMEM>>>(
        (const __half*)pXh, (const __half*)pW1T, b1, (__half*)pH1,
        DIN_, DH_, 0, 0);

    gemm_fp16<false, true, 2><<<dim3(N_ / BN, DH_ / BM, B_), 256, GEMM_SMEM>>>(
        (const __half*)pW2T, (const __half*)pH1, b2, (__half*)pET,
        DH_, N_, (size_t)N_ * DH_, (size_t)DH_ * N_);

    select_kernel<<<(B_ * DH_) / 8, 256>>>();
    decode1_kernel<<<dim3(8, 16), 128>>>(W3, b3);
    decode2_kernel<<<80, 256>>>(W4, b4, out);
}

// round 12
// speedup vs baseline: 1.6760x; 1.0096x over previous
#include <cuda_runtime.h>
#include <cuda_fp16.h>
#include <cstdint>
#include <cstddef>

#define B_    64
#define N_    1024
#define DIN_  512
#define DH_   1024

#define BM 128
#define BN 128
#define BK 64
#define SSTRIDE 72           // fp16 elems per smem row: 64 data + 8 pad (144B)
#define TS 3
#define STAGE_HALFS ((BM + BN) * SSTRIDE)   // 18432 halfs = 36864 B
#define GEMM_SMEM (TS * STAGE_HALFS * 2)    // 110592 B

// prep kernel block partition
#define PREP_CAST_BLKS 32768
#define PREP_W1_BASE   PREP_CAST_BLKS
#define PREP_W1_BLKS   512
#define PREP_W2_BASE   (PREP_W1_BASE + PREP_W1_BLKS)
#define PREP_W2_BLKS   1024
#define PREP_NV_BASE   (PREP_W2_BASE + PREP_W2_BLKS)
#define PREP_NV_BLKS   64
#define PREP_TOTAL     (PREP_NV_BASE + PREP_NV_BLKS)

// ------------------------- static device scratch -------------------------
__device__ __half g_Xh[(size_t)B_ * N_ * DIN_];
__device__ __half g_W1T[(size_t)DH_ * DIN_];
__device__ __half g_W2T[(size_t)DH_ * DH_];
__device__ __half g_H1[(size_t)B_ * N_ * DH_];
__device__ __half g_ET[(size_t)B_ * DH_ * N_];
__device__ float  g_agg[B_ * DH_];
__device__ float  g_T[B_ * DH_];
__device__ int    g_nv[B_];
__device__ int    g_kk[B_];

// ------------------------- helpers -------------------------
__device__ __forceinline__ float keyToFloat16(unsigned k32) {
    unsigned t = k32 >> 16;
    unsigned short b = (t & 0x8000u) ? (unsigned short)(t ^ 0x8000u)
                                     : (unsigned short)(~t & 0xFFFFu);
    return __half2float(__ushort_as_half(b));
}

__device__ __forceinline__ void mma16816(float* c, const uint32_t* a, uint32_t b0, uint32_t b1) {
    asm volatile(
        "mma.sync.aligned.m16n8k16.row.col.f32.f16.f16.f32 "
        "{%0,%1,%2,%3},{%4,%5,%6,%7},{%8,%9},{%0,%1,%2,%3};\n"
        : "+f"(c[0]), "+f"(c[1]), "+f"(c[2]), "+f"(c[3])
        : "r"(a[0]), "r"(a[1]), "r"(a[2]), "r"(a[3]), "r"(b0), "r"(b1));
}
__device__ __forceinline__ void ldmat4(uint32_t* r, uint32_t addr) {
    asm volatile("ldmatrix.sync.aligned.m8n8.x4.shared.b16 {%0,%1,%2,%3},[%4];\n"
                 : "=r"(r[0]), "=r"(r[1]), "=r"(r[2]), "=r"(r[3])
                 : "r"(addr));
}
#define CP16(dst, src) asm volatile("cp.async.cg.shared.global [%0],[%1],16;\n" ::"r"(dst), "l"(src))

// Half bit-transpose on packed keys (in place). pk[m] holds two 16-bit keys
// (high/low halfwords). Stages J=8,4,2,1 complete the 32x32 transpose
// restricted to the 16 meaningful words; popc-based ranking is agnostic to
// the within-plane bit permutation, so only counts matter.
template <int J>
__device__ __forceinline__ void tstep16(unsigned* A, unsigned m) {
#pragma unroll
    for (int k0 = 0; k0 < 8; k0++) {
        int k = ((k0 & ~(J - 1)) << 1) | (k0 & (J - 1));
        unsigned t = (A[k] ^ (A[k + J] >> J)) & m;
        A[k] ^= t;
        A[k + J] ^= (t << J);
    }
}
__device__ __forceinline__ void half_transpose_packed(unsigned* planes) {
    tstep16<8>(planes, 0x00FF00FFu);
    tstep16<4>(planes, 0x0F0F0F0Fu);
    tstep16<2>(planes, 0x33333333u);
    tstep16<1>(planes, 0x55555555u);
}

// Fused dual radix descent: keys at ranks r1 <= r2 over the warp's 1024 keys.
// Residual ranks r1f/r2f = rank within the equal-key set (tie correction).
__device__ __forceinline__ void radix_dual(const unsigned* planes, int r1, int r2,
                                           unsigned& T1, unsigned& T2, int& r1f, int& r2f) {
    unsigned C1 = 0xFFFFFFFFu, C2 = 0xFFFFFFFFu, p1 = 0u, p2 = 0u;
#pragma unroll
    for (int bit = 31; bit >= 16; --bit) {
        unsigned P = planes[31 - bit];
        unsigned z1 = C1 & ~P;
        unsigned z2 = C2 & ~P;
        unsigned tot = __reduce_add_sync(0xFFFFFFFFu,
                                         (unsigned)__popc(z1) + ((unsigned)__popc(z2) << 16));
        int c1 = (int)(tot & 0xFFFFu), c2 = (int)(tot >> 16);
        if (r1 < c1) { C1 = z1; } else { r1 -= c1; C1 &= P; p1 |= (1u << bit); }
        if (r2 < c2) { C2 = z2; } else { r2 -= c2; C2 &= P; p2 |= (1u << bit); }
    }
    T1 = p1; T2 = p2; r1f = r1; r2f = r2;
}

// ------------------------- fused prep kernel -------------------------
__global__ void __launch_bounds__(256) prep_kernel(
    const float* __restrict__ X, const float* __restrict__ mask,
    const float* __restrict__ W1, const float* __restrict__ W2) {
    __shared__ float tile[32][33];
    const int bid = blockIdx.x;
    const int tid = threadIdx.x;

    if (bid < PREP_CAST_BLKS) {
        int i = bid * 256 + tid;       // float4 index
        int row = i >> 7;              // 128 float4 per row
        if (mask[row] > 0.0f) {
            float4 v = ((const float4*)X)[i];
            __half2* p = (__half2*)&g_Xh[4 * (size_t)i];
            p[0] = __floats2half2_rn(v.x, v.y);
            p[1] = __floats2half2_rn(v.z, v.w);
        }
        return;
    }

    if (bid < PREP_NV_BASE) {
        const float* W;
        __half* WT;
        int Krows, local;
        if (bid < PREP_W2_BASE) {
            local = bid - PREP_W1_BASE;
            W = W1;
            Krows = DIN_;
            WT = g_W1T;
        } else {
            local = bid - PREP_W2_BASE;
            W = W2;
            Krows = DH_;
            WT = g_W2T;
        }
        int bx = local & 31, by = local >> 5;
        int tx = tid & 31, ty = tid >> 5;
#pragma unroll
        for (int i = 0; i < 32; i += 8) {
            int y = by * 32 + ty + i;
            tile[ty + i][tx] = W[(size_t)y * DH_ + bx * 32 + tx];
        }
        __syncthreads();
        int xo = by * 32 + tx;
#pragma unroll
        for (int i = 0; i < 32; i += 8) {
            int yo = bx * 32 + ty + i;
            WT[(size_t)yo * Krows + xo] = __float2half_rn(tile[tx][ty + i]);
        }
        return;
    }

    {
        int b = bid - PREP_NV_BASE;
        __shared__ int cnt;
        if (tid == 0) cnt = 0;
        __syncthreads();
        int lane = tid & 31, w = tid >> 5;
        int local = 0;
#pragma unroll
        for (int j = 0; j < 4; j++) {
            int widx = w + 8 * j;
            int n = widx * 32 + lane;
            int v = mask[(size_t)b * N_ + n] > 0.0f;
            unsigned word = __ballot_sync(0xFFFFFFFFu, v);
            if (lane == 0) local += __popc(word);
        }
        if (lane == 0 && local) atomicAdd(&cnt, local);
        __syncthreads();
        if (tid == 0) {
            g_nv[b] = cnt;
            g_kk[b] = (int)((float)cnt * 0.1f);
        }
    }
}

// ------------------------- main GEMM (fp16 MMA, fp32 accum) -------------
template <bool RELU, bool BIAS_BY_ROW, int SKIP_MODE>
__global__ void __launch_bounds__(256, 2) gemm_fp16(
    const __half* __restrict__ A, const __half* __restrict__ B,
    const float* __restrict__ bias, __half* __restrict__ out,
    int K, int N, size_t zB, size_t zC) {
    extern __shared__ __half sm[];

    const int mBase = blockIdx.y * BM, nBase = blockIdx.x * BN;
    if (SKIP_MODE == 1) {
        if ((mBase & (N_ - 1)) >= g_nv[mBase >> 10]) return;
    } else if (SKIP_MODE == 2) {
        if (nBase >= g_nv[blockIdx.z]) return;
    }

    B += (size_t)blockIdx.z * zB;
    out += (size_t)blockIdx.z * zC;

    const int tid = threadIdx.x;
    const int lane = tid & 31;
    const int wid = tid >> 5;
    const int wm = (wid >> 2) * 64;
    const int wn = (wid & 3) * 32;
    const int gq = lane >> 2, tg = lane & 3;
    const int KT = K / BK;

    float acc[4][4][4];
#pragma unroll
    for (int a = 0; a < 4; a++)
#pragma unroll
        for (int b = 0; b < 4; b++)
#pragma unroll
            for (int c = 0; c < 4; c++) acc[a][b][c] = 0.f;

    auto load = [&](int kt, int s) {
        __half* sa = sm + s * STAGE_HALFS;
        int k0 = kt * BK;
#pragma unroll
        for (int p = 0; p < 8; p++) {
            int v = tid + 256 * p;
            int row = v >> 3;
            int cv = (v & 7) * 8;
            uint32_t d = (uint32_t)__cvta_generic_to_shared(sa + row * SSTRIDE + cv);
            const __half* src = (row < BM) ? (A + (size_t)(mBase + row) * K + k0 + cv)
                                           : (B + (size_t)(nBase + row - BM) * K + k0 + cv);
            CP16(d, src);
        }
        asm volatile("cp.async.commit_group;\n");
    };

    load(0, 0);
    if (KT > 1) load(1, 1);
    for (int kt = 0; kt < KT; kt++) {
        int s = kt % TS;
        if (kt + 1 < KT) {
            asm volatile("cp.async.wait_group 1;\n");
        } else {
            asm volatile("cp.async.wait_group 0;\n");
        }
        __syncthreads();
        if (kt + 2 < KT) load(kt + 2, (kt + 2) % TS);

        const __half* sa = sm + s * STAGE_HALFS;
        const __half* sb = sa + BM * SSTRIDE;
#pragma unroll
        for (int kk = 0; kk < BK; kk += 16) {
            uint32_t af[4][4];
#pragma unroll
            for (int mi = 0; mi < 4; mi++) {
                uint32_t ad = (uint32_t)__cvta_generic_to_shared(
                    sa + (wm + mi * 16 + (lane & 15)) * SSTRIDE + kk + (lane >> 4) * 8);
                ldmat4(af[mi], ad);
            }
#pragma unroll
            for (int ni = 0; ni < 4; ni++) {
                const __half* bp = sb + (wn + ni * 8 + gq) * SSTRIDE + kk + 2 * tg;
                uint32_t b0 = *(const uint32_t*)bp;
                uint32_t b1v = *(const uint32_t*)(bp + 8);
#pragma unroll
                for (int mi = 0; mi < 4; mi++) mma16816(acc[mi][ni], af[mi], b0, b1v);
            }
        }
    }

#pragma unroll
    for (int mi = 0; mi < 4; mi++) {
        int r0 = mBase + wm + mi * 16 + gq;
        float bvR0 = 0.f, bvR1 = 0.f;
        if (BIAS_BY_ROW) { bvR0 = bias[r0]; bvR1 = bias[r0 + 8]; }
#pragma unroll
        for (int ni = 0; ni < 4; ni++) {
            int col = nBase + wn + ni * 8 + 2 * tg;
            float v00, v01, v10, v11;
            if (BIAS_BY_ROW) {
                v00 = acc[mi][ni][0] + bvR0; v01 = acc[mi][ni][1] + bvR0;
                v10 = acc[mi][ni][2] + bvR1; v11 = acc[mi][ni][3] + bvR1;
            } else {
                float bv0 = bias[col], bv1 = bias[col + 1];
                v00 = acc[mi][ni][0] + bv0; v01 = acc[mi][ni][1] + bv1;
                v10 = acc[mi][ni][2] + bv0; v11 = acc[mi][ni][3] + bv1;
            }
            if (RELU) {
                v00 = fmaxf(v00, 0.f); v01 = fmaxf(v01, 0.f);
                v10 = fmaxf(v10, 0.f); v11 = fmaxf(v11, 0.f);
            }
            *(__half2*)(out + (size_t)r0 * N + col) = __floats2half2_rn(v00, v01);
            *(__half2*)(out + (size_t)(r0 + 8) * N + col) = __floats2half2_rn(v10, v11);
        }
    }
}

// ------------------------- trimmed-mean select -------------------------
// Prefix mask: valid <=> n < nv (nv >= 512 => kT >= 51 > 0 always).
// Values kept packed in registers; invalid lanes masked to fp16 NaN (0x7FFF),
// which maps to key 0xFFFF (above all finite keys). The band test runs on the
// float values directly: v >= v1 && v < v2 is exactly the key test
// T1 <= kv < T2 (strictly monotone map; +-0 contribute 0 either way; NaN
// fails both compares).
__global__ void __launch_bounds__(256) select_kernel() {
    int warp = (blockIdx.x << 3) + (threadIdx.x >> 5);  // b*1024 + h
    int lane = threadIdx.x & 31;
    int b = warp >> 10;
    const __half* col = g_ET + ((size_t)warp << 10);

    int nv = g_nv[b], kT = g_kk[b];

    unsigned vals[16], pk[16];
#pragma unroll
    for (int j = 0; j < 4; j++) {
        int n0 = j * 256 + lane * 8;
        if (j * 256 >= nv) {  // whole chunk beyond valid prefix
#pragma unroll
            for (int i = 0; i < 4; i++) vals[j * 4 + i] = 0x7FFF7FFFu;
        } else {
            uint4 v = *(const uint4*)(col + n0);
            vals[j * 4 + 0] = v.x; vals[j * 4 + 1] = v.y;
            vals[j * 4 + 2] = v.z; vals[j * 4 + 3] = v.w;
            int rr = nv - n0;  // valid count among this lane's 8
            if (rr < 8) {      // rare boundary fixup: invalid halves -> NaN
#pragma unroll
                for (int i = 0; i < 4; i++) {
                    unsigned fm = ((2 * i >= rr) ? 0x0000FFFFu : 0u)
                                | ((2 * i + 1 >= rr) ? 0xFFFF0000u : 0u);
                    vals[j * 4 + i] = (vals[j * 4 + i] & ~fm) | (0x7FFF7FFFu & fm);
                }
            }
        }
#pragma unroll
        for (int i = 0; i < 4; i++) {
            unsigned hh = vals[j * 4 + i];
            unsigned t = hh & 0x80008000u;
            unsigned m = (t >> 15) * 0x7FFFu;
            pk[j * 4 + i] = hh ^ (m | 0x80008000u);  // monotone fp16->u16, SIMD
        }
    }

    half_transpose_packed(pk);  // pk -> bit planes (consumed by radix)

    unsigned T1, T2;
    int r1f, r2f;
    radix_dual(pk, kT - 1, nv - kT - 1, T1, T2, r1f, r2f);

    float v1 = keyToFloat16(T1), v2 = keyToFloat16(T2);

    // band sum over values with v1 <= v < v2 (== T1 <= key < T2)
    float s = 0.f;
#pragma unroll
    for (int m = 0; m < 16; m++) {
        float2 f = __half22float2(*reinterpret_cast<__half2*>(&vals[m]));
        if (f.x >= v1 && f.x < v2) s += f.x;
        if (f.y >= v1 && f.y < v2) s += f.y;
    }
#pragma unroll
    for (int o = 16; o; o >>= 1) s += __shfl_xor_sync(0xFFFFFFFFu, s, o);

    if (lane == 0) {
        g_agg[warp] = (s + (float)(r2f + 1) * v2 - (float)(r1f + 1) * v1)
                      / (float)(nv - 2 * kT);
    }
}

// ------------------------- decode MLP -------------------------
__global__ void __launch_bounds__(128) decode1_kernel(const float* __restrict__ W3,
                                                      const float* __restrict__ b3) {
    __shared__ float sa[4][1024];
    int h = blockIdx.x * 128 + threadIdx.x;
    int bg = blockIdx.y * 4;
    for (int i = threadIdx.x; i < 4 * 1024; i += 128)
        sa[i >> 10][i & 1023] = g_agg[(bg + (i >> 10)) * 1024 + (i & 1023)];
    __syncthreads();
    float accv[4] = {0.f, 0.f, 0.f, 0.f};
    for (int k2 = 0; k2 < 1024; k2++) {
        float w = W3[(size_t)k2 * 1024 + h];
#pragma unroll
        for (int ii = 0; ii < 4; ii++) accv[ii] += sa[ii][k2] * w;
    }
    float bb = b3[h];
#pragma unroll
    for (int ii = 0; ii < 4; ii++) g_T[(bg + ii) * 1024 + h] = fmaxf(accv[ii] + bb, 0.f);
}

__global__ void decode2_kernel(const float* __restrict__ W4, const float* __restrict__ b4,
                               float* __restrict__ out) {
    int gw = blockIdx.x * 8 + (threadIdx.x >> 5);
    int lane = threadIdx.x & 31;
    if (gw >= 640) return;
    int b = gw / 10, o = gw - 10 * b;
    float acc = 0.f;
#pragma unroll
    for (int i = 0; i < 32; i++) {
        int kidx = i * 32 + lane;
        acc += g_T[b * 1024 + kidx] * W4[(size_t)kidx * 10 + o];
    }
#pragma unroll
    for (int oo = 16; oo; oo >>= 1) acc += __shfl_xor_sync(0xFFFFFFFFu, acc, oo);
    if (lane == 0) out[b * 10 + o] = acc + b4[o];
}

// ------------------------- launch -------------------------
extern "C" void kernel_launch(void* const* d_in, const int* in_sizes, int n_in,
                              void* d_out, int out_size) {
    const float* X = (const float*)d_in[0];
    const float* mask = (const float*)d_in[1];
    const float* W1 = (const float*)d_in[2];
    const float* b1 = (const float*)d_in[3];
    const float* W2 = (const float*)d_in[4];
    const float* b2 = (const float*)d_in[5];
    const float* W3 = (const float*)d_in[6];
    const float* b3 = (const float*)d_in[7];
    const float* W4 = (const float*)d_in[8];
    const float* b4 = (const float*)d_in[9];
    float* out = (float*)d_out;

    void *pXh, *pW1T, *pW2T, *pH1, *pET;
    cudaGetSymbolAddress(&pXh, g_Xh);
    cudaGetSymbolAddress(&pW1T, g_W1T);
    cudaGetSymbolAddress(&pW2T, g_W2T);
    cudaGetSymbolAddress(&pH1, g_H1);
    cudaGetSymbolAddress(&pET, g_ET);

    cudaFuncSetAttribute(gemm_fp16<true, false, 1>, cudaFuncAttributeMaxDynamicSharedMemorySize, GEMM_SMEM);
    cudaFuncSetAttribute(gemm_fp16<false, true, 2>, cudaFuncAttributeMaxDynamicSharedMemorySize, GEMM_SMEM);

    prep_kernel<<<PREP_TOTAL, 256>>>(X, mask, W1, W2);

    gemm_fp16<true, false, 1><<<dim3(DH_ / BN, (B_ * N_) / BM, 1), 256, GEMM_SMEM>>>(
        (const __half*)pXh, (const __half*)pW1T, b1, (__half*)pH1,
        DIN_, DH_, 0, 0);

    gemm_fp16<false, true, 2><<<dim3(N_ / BN, DH_ / BM, B_), 256, GEMM_SMEM>>>(
        (const __half*)pW2T, (const __half*)pH1, b2, (__half*)pET,
        DH_, N_, (size_t)N_ * DH_, (size_t)DH_ * N_);

    select_kernel<<<(B_ * DH_) / 8, 256>>>();
    decode1_kernel<<<dim3(8, 16), 128>>>(W3, b3);
    decode2_kernel<<<80, 256>>>(W4, b4, out);
}

// round 14
// speedup vs baseline: 1.7495x; 1.0438x over previous
#include <cuda_runtime.h>
#include <cuda_fp16.h>
#include <cstdint>
#include <cstddef>

#define B_    64
#define N_    1024
#define DIN_  512
#define DH_   1024
#define HB    32            // batches per half-pipeline

#define BM 128
#define BN 128
#define BK 64
#define SSTRIDE 72           // fp16 elems per smem row: 64 data + 8 pad (144B)
#define TS 3
#define STAGE_HALFS ((BM + BN) * SSTRIDE)   // 18432 halfs = 36864 B
#define GEMM_SMEM (TS * STAGE_HALFS * 2)    // 110592 B

// prep kernel block partition
#define PREP_CAST_BLKS 32768
#define PREP_W1_BASE   PREP_CAST_BLKS
#define PREP_W1_BLKS   512
#define PREP_W2_BASE   (PREP_W1_BASE + PREP_W1_BLKS)
#define PREP_W2_BLKS   1024
#define PREP_NV_BASE   (PREP_W2_BASE + PREP_W2_BLKS)
#define PREP_NV_BLKS   64
#define PREP_TOTAL     (PREP_NV_BASE + PREP_NV_BLKS)

// ------------------------- static device scratch -------------------------
__device__ __half g_Xh[(size_t)B_ * N_ * DIN_];
__device__ __half g_W1T[(size_t)DH_ * DIN_];
__device__ __half g_W2T[(size_t)DH_ * DH_];
__device__ __half g_H1[(size_t)B_ * N_ * DH_];
__device__ __half g_ET[(size_t)B_ * DH_ * N_];
__device__ float  g_agg[B_ * DH_];
__device__ float  g_T[B_ * DH_];
__device__ int    g_nv[B_];
__device__ int    g_kk[B_];

// ------------------------- helpers -------------------------
__device__ __forceinline__ float keyToFloat16(unsigned k32) {
    unsigned t = k32 >> 16;
    unsigned short b = (t & 0x8000u) ? (unsigned short)(t ^ 0x8000u)
                                     : (unsigned short)(~t & 0xFFFFu);
    return __half2float(__ushort_as_half(b));
}

__device__ __forceinline__ void mma16816(float* c, const uint32_t* a, uint32_t b0, uint32_t b1) {
    asm volatile(
        "mma.sync.aligned.m16n8k16.row.col.f32.f16.f16.f32 "
        "{%0,%1,%2,%3},{%4,%5,%6,%7},{%8,%9},{%0,%1,%2,%3};\n"
        : "+f"(c[0]), "+f"(c[1]), "+f"(c[2]), "+f"(c[3])
        : "r"(a[0]), "r"(a[1]), "r"(a[2]), "r"(a[3]), "r"(b0), "r"(b1));
}
__device__ __forceinline__ void ldmat4(uint32_t* r, uint32_t addr) {
    asm volatile("ldmatrix.sync.aligned.m8n8.x4.shared.b16 {%0,%1,%2,%3},[%4];\n"
                 : "=r"(r[0]), "=r"(r[1]), "=r"(r[2]), "=r"(r[3])
                 : "r"(addr));
}
#define CP16(dst, src) asm volatile("cp.async.cg.shared.global [%0],[%1],16;\n" ::"r"(dst), "l"(src))

// Half bit-transpose on packed keys (in place), 16 words.
template <int J>
__device__ __forceinline__ void tstep16(unsigned* A, unsigned m) {
#pragma unroll
    for (int k0 = 0; k0 < 8; k0++) {
        int k = ((k0 & ~(J - 1)) << 1) | (k0 & (J - 1));
        unsigned t = (A[k] ^ (A[k + J] >> J)) & m;
        A[k] ^= t;
        A[k + J] ^= (t << J);
    }
}
__device__ __forceinline__ void half_transpose_packed(unsigned* planes) {
    tstep16<8>(planes, 0x00FF00FFu);
    tstep16<4>(planes, 0x0F0F0F0Fu);
    tstep16<2>(planes, 0x33333333u);
    tstep16<1>(planes, 0x55555555u);
}

// Fused dual radix descent; residual ranks r1f/r2f for exact tie correction.
__device__ __forceinline__ void radix_dual(const unsigned* planes, int r1, int r2,
                                           unsigned& T1, unsigned& T2, int& r1f, int& r2f) {
    unsigned C1 = 0xFFFFFFFFu, C2 = 0xFFFFFFFFu, p1 = 0u, p2 = 0u;
#pragma unroll
    for (int bit = 31; bit >= 16; --bit) {
        unsigned P = planes[31 - bit];
        unsigned z1 = C1 & ~P;
        unsigned z2 = C2 & ~P;
        unsigned tot = __reduce_add_sync(0xFFFFFFFFu,
                                         (unsigned)__popc(z1) + ((unsigned)__popc(z2) << 16));
        int c1 = (int)(tot & 0xFFFFu), c2 = (int)(tot >> 16);
        if (r1 < c1) { C1 = z1; } else { r1 -= c1; C1 &= P; p1 |= (1u << bit); }
        if (r2 < c2) { C2 = z2; } else { r2 -= c2; C2 &= P; p2 |= (1u << bit); }
    }
    T1 = p1; T2 = p2; r1f = r1; r2f = r2;
}

// ------------------------- fused prep kernel -------------------------
__global__ void __launch_bounds__(256) prep_kernel(
    const float* __restrict__ X, const float* __restrict__ mask,
    const float* __restrict__ W1, const float* __restrict__ W2) {
    __shared__ float tile[32][33];
    const int bid = blockIdx.x;
    const int tid = threadIdx.x;

    if (bid < PREP_CAST_BLKS) {
        int i = bid * 256 + tid;       // float4 index
        int row = i >> 7;              // 128 float4 per row
        if (mask[row] > 0.0f) {
            float4 v = ((const float4*)X)[i];
            __half2* p = (__half2*)&g_Xh[4 * (size_t)i];
            p[0] = __floats2half2_rn(v.x, v.y);
            p[1] = __floats2half2_rn(v.z, v.w);
        }
        return;
    }

    if (bid < PREP_NV_BASE) {
        const float* W;
        __half* WT;
        int Krows, local;
        if (bid < PREP_W2_BASE) {
            local = bid - PREP_W1_BASE;
            W = W1;
            Krows = DIN_;
            WT = g_W1T;
        } else {
            local = bid - PREP_W2_BASE;
            W = W2;
            Krows = DH_;
            WT = g_W2T;
        }
        int bx = local & 31, by = local >> 5;
        int tx = tid & 31, ty = tid >> 5;
#pragma unroll
        for (int i = 0; i < 32; i += 8) {
            int y = by * 32 + ty + i;
            tile[ty + i][tx] = W[(size_t)y * DH_ + bx * 32 + tx];
        }
        __syncthreads();
        int xo = by * 32 + tx;
#pragma unroll
        for (int i = 0; i < 32; i += 8) {
            int yo = bx * 32 + ty + i;
            WT[(size_t)yo * Krows + xo] = __float2half_rn(tile[tx][ty + i]);
        }
        return;
    }

    {
        int b = bid - PREP_NV_BASE;
        __shared__ int cnt;
        if (tid == 0) cnt = 0;
        __syncthreads();
        int lane = tid & 31, w = tid >> 5;
        int local = 0;
#pragma unroll
        for (int j = 0; j < 4; j++) {
            int widx = w + 8 * j;
            int n = widx * 32 + lane;
            int v = mask[(size_t)b * N_ + n] > 0.0f;
            unsigned word = __ballot_sync(0xFFFFFFFFu, v);
            if (lane == 0) local += __popc(word);
        }
        if (lane == 0 && local) atomicAdd(&cnt, local);
        __syncthreads();
        if (tid == 0) {
            g_nv[b] = cnt;
            g_kk[b] = (int)((float)cnt * 0.1f);
        }
    }
}

// ------------------------- main GEMM (fp16 MMA, fp32 accum) -------------
// Operates on a half-pipeline: all pointers pre-offset; nvp indexed locally.
// SKIP_MODE 1: skip if (mBase&1023) >= nvp[mBase>>10] (GEMM1);
//           2: skip if nBase >= nvp[blockIdx.z] (GEMM2).
template <bool RELU, bool BIAS_BY_ROW, int SKIP_MODE>
__global__ void __launch_bounds__(256, 2) gemm_fp16(
    const __half* __restrict__ A, const __half* __restrict__ B,
    const float* __restrict__ bias, __half* __restrict__ out,
    const int* __restrict__ nvp, int K, int N, size_t zB, size_t zC) {
    extern __shared__ __half sm[];

    const int mBase = blockIdx.y * BM, nBase = blockIdx.x * BN;
    if (SKIP_MODE == 1) {
        if ((mBase & (N_ - 1)) >= nvp[mBase >> 10]) return;
    } else if (SKIP_MODE == 2) {
        if (nBase >= nvp[blockIdx.z]) return;
    }

    B += (size_t)blockIdx.z * zB;
    out += (size_t)blockIdx.z * zC;

    const int tid = threadIdx.x;
    const int lane = tid & 31;
    const int wid = tid >> 5;
    const int wm = (wid >> 2) * 64;
    const int wn = (wid & 3) * 32;
    const int gq = lane >> 2, tg = lane & 3;
    const int KT = K / BK;

    float acc[4][4][4];
#pragma unroll
    for (int a = 0; a < 4; a++)
#pragma unroll
        for (int b = 0; b < 4; b++)
#pragma unroll
            for (int c = 0; c < 4; c++) acc[a][b][c] = 0.f;

    auto load = [&](int kt, int s) {
        __half* sa = sm + s * STAGE_HALFS;
        int k0 = kt * BK;
#pragma unroll
        for (int p = 0; p < 8; p++) {
            int v = tid + 256 * p;
            int row = v >> 3;
            int cv = (v & 7) * 8;
            uint32_t d = (uint32_t)__cvta_generic_to_shared(sa + row * SSTRIDE + cv);
            const __half* src = (row < BM) ? (A + (size_t)(mBase + row) * K + k0 + cv)
                                           : (B + (size_t)(nBase + row - BM) * K + k0 + cv);
            CP16(d, src);
        }
        asm volatile("cp.async.commit_group;\n");
    };

    load(0, 0);
    if (KT > 1) load(1, 1);
    for (int kt = 0; kt < KT; kt++) {
        int s = kt % TS;
        if (kt + 1 < KT) {
            asm volatile("cp.async.wait_group 1;\n");
        } else {
            asm volatile("cp.async.wait_group 0;\n");
        }
        __syncthreads();
        if (kt + 2 < KT) load(kt + 2, (kt + 2) % TS);

        const __half* sa = sm + s * STAGE_HALFS;
        const __half* sb = sa + BM * SSTRIDE;
#pragma unroll
        for (int kk = 0; kk < BK; kk += 16) {
            uint32_t af[4][4];
#pragma unroll
            for (int mi = 0; mi < 4; mi++) {
                uint32_t ad = (uint32_t)__cvta_generic_to_shared(
                    sa + (wm + mi * 16 + (lane & 15)) * SSTRIDE + kk + (lane >> 4) * 8);
                ldmat4(af[mi], ad);
            }
#pragma unroll
            for (int ni = 0; ni < 4; ni++) {
                const __half* bp = sb + (wn + ni * 8 + gq) * SSTRIDE + kk + 2 * tg;
                uint32_t b0 = *(const uint32_t*)bp;
                uint32_t b1v = *(const uint32_t*)(bp + 8);
#pragma unroll
                for (int mi = 0; mi < 4; mi++) mma16816(acc[mi][ni], af[mi], b0, b1v);
            }
        }
    }

#pragma unroll
    for (int mi = 0; mi < 4; mi++) {
        int r0 = mBase + wm + mi * 16 + gq;
        float bvR0 = 0.f, bvR1 = 0.f;
        if (BIAS_BY_ROW) { bvR0 = bias[r0]; bvR1 = bias[r0 + 8]; }
#pragma unroll
        for (int ni = 0; ni < 4; ni++) {
            int col = nBase + wn + ni * 8 + 2 * tg;
            float v00, v01, v10, v11;
            if (BIAS_BY_ROW) {
                v00 = acc[mi][ni][0] + bvR0; v01 = acc[mi][ni][1] + bvR0;
                v10 = acc[mi][ni][2] + bvR1; v11 = acc[mi][ni][3] + bvR1;
            } else {
                float bv0 = bias[col], bv1 = bias[col + 1];
                v00 = acc[mi][ni][0] + bv0; v01 = acc[mi][ni][1] + bv1;
                v10 = acc[mi][ni][2] + bv0; v11 = acc[mi][ni][3] + bv1;
            }
            if (RELU) {
                v00 = fmaxf(v00, 0.f); v01 = fmaxf(v01, 0.f);
                v10 = fmaxf(v10, 0.f); v11 = fmaxf(v11, 0.f);
            }
            *(__half2*)(out + (size_t)r0 * N + col) = __floats2half2_rn(v00, v01);
            *(__half2*)(out + (size_t)(r0 + 8) * N + col) = __floats2half2_rn(v10, v11);
        }
    }
}

// ------------------------- trimmed-mean select (half-pipeline) ----------
__global__ void __launch_bounds__(256) select_kernel(
    const __half* __restrict__ ET, float* __restrict__ agg,
    const int* __restrict__ nvp, const int* __restrict__ kkp) {
    int warp = (blockIdx.x << 3) + (threadIdx.x >> 5);  // b_local*1024 + h
    int lane = threadIdx.x & 31;
    int b = warp >> 10;
    const __half* col = ET + ((size_t)warp << 10);

    int nv = nvp[b], kT = kkp[b];

    unsigned vals[16], pk[16];
#pragma unroll
    for (int j = 0; j < 4; j++) {
        int n0 = j * 256 + lane * 8;
        if (j * 256 >= nv) {
#pragma unroll
            for (int i = 0; i < 4; i++) vals[j * 4 + i] = 0x7FFF7FFFu;
        } else {
            uint4 v = *(const uint4*)(col + n0);
            vals[j * 4 + 0] = v.x; vals[j * 4 + 1] = v.y;
            vals[j * 4 + 2] = v.z; vals[j * 4 + 3] = v.w;
            int rr = nv - n0;
            if (rr < 8) {
#pragma unroll
                for (int i = 0; i < 4; i++) {
                    unsigned fm = ((2 * i >= rr) ? 0x0000FFFFu : 0u)
                                | ((2 * i + 1 >= rr) ? 0xFFFF0000u : 0u);
                    vals[j * 4 + i] = (vals[j * 4 + i] & ~fm) | (0x7FFF7FFFu & fm);
                }
            }
        }
#pragma unroll
        for (int i = 0; i < 4; i++) {
            unsigned hh = vals[j * 4 + i];
            unsigned t = hh & 0x80008000u;
            unsigned m = (t >> 15) * 0x7FFFu;
            pk[j * 4 + i] = hh ^ (m | 0x80008000u);
        }
    }

    half_transpose_packed(pk);

    unsigned T1, T2;
    int r1f, r2f;
    radix_dual(pk, kT - 1, nv - kT - 1, T1, T2, r1f, r2f);

    float v1 = keyToFloat16(T1), v2 = keyToFloat16(T2);

    float s = 0.f;
#pragma unroll
    for (int m = 0; m < 16; m++) {
        float2 f = __half22float2(*reinterpret_cast<__half2*>(&vals[m]));
        if (f.x >= v1 && f.x < v2) s += f.x;
        if (f.y >= v1 && f.y < v2) s += f.y;
    }
#pragma unroll
    for (int o = 16; o; o >>= 1) s += __shfl_xor_sync(0xFFFFFFFFu, s, o);

    if (lane == 0) {
        agg[warp] = (s + (float)(r2f + 1) * v2 - (float)(r1f + 1) * v1)
                    / (float)(nv - 2 * kT);
    }
}

// ------------------------- decode MLP (half-pipeline) -------------------
__global__ void __launch_bounds__(128) decode1_kernel(
    const float* __restrict__ W3, const float* __restrict__ b3,
    const float* __restrict__ agg, float* __restrict__ T) {
    __shared__ float sa[4][1024];
    int h = blockIdx.x * 128 + threadIdx.x;
    int bg = blockIdx.y * 4;
    for (int i = threadIdx.x; i < 4 * 1024; i += 128)
        sa[i >> 10][i & 1023] = agg[(bg + (i >> 10)) * 1024 + (i & 1023)];
    __syncthreads();
    float accv[4] = {0.f, 0.f, 0.f, 0.f};
    for (int k2 = 0; k2 < 1024; k2++) {
        float w = W3[(size_t)k2 * 1024 + h];
#pragma unroll
        for (int ii = 0; ii < 4; ii++) accv[ii] += sa[ii][k2] * w;
    }
    float bb = b3[h];
#pragma unroll
    for (int ii = 0; ii < 4; ii++) T[(bg + ii) * 1024 + h] = fmaxf(accv[ii] + bb, 0.f);
}

__global__ void decode2_kernel(const float* __restrict__ W4, const float* __restrict__ b4,
                               const float* __restrict__ T, float* __restrict__ out) {
    int gw = blockIdx.x * 8 + (threadIdx.x >> 5);
    int lane = threadIdx.x & 31;
    if (gw >= HB * 10) return;
    int b = gw / 10, o = gw - 10 * b;
    float acc = 0.f;
#pragma unroll
    for (int i = 0; i < 32; i++) {
        int kidx = i * 32 + lane;
        acc += T[b * 1024 + kidx] * W4[(size_t)kidx * 10 + o];
    }
#pragma unroll
    for (int oo = 16; oo; oo >>= 1) acc += __shfl_xor_sync(0xFFFFFFFFu, acc, oo);
    if (lane == 0) out[b * 10 + o] = acc + b4[o];
}

// ------------------------- launch -------------------------
extern "C" void kernel_launch(void* const* d_in, const int* in_sizes, int n_in,
                              void* d_out, int out_size) {
    const float* X = (const float*)d_in[0];
    const float* mask = (const float*)d_in[1];
    const float* W1 = (const float*)d_in[2];
    const float* b1 = (const float*)d_in[3];
    const float* W2 = (const float*)d_in[4];
    const float* b2 = (const float*)d_in[5];
    const float* W3 = (const float*)d_in[6];
    const float* b3 = (const float*)d_in[7];
    const float* W4 = (const float*)d_in[8];
    const float* b4 = (const float*)d_in[9];
    float* out = (float*)d_out;

    void *pXh, *pW1T, *pW2T, *pH1, *pET, *pAgg, *pT, *pNv, *pKk;
    cudaGetSymbolAddress(&pXh, g_Xh);
    cudaGetSymbolAddress(&pW1T, g_W1T);
    cudaGetSymbolAddress(&pW2T, g_W2T);
    cudaGetSymbolAddress(&pH1, g_H1);
    cudaGetSymbolAddress(&pET, g_ET);
    cudaGetSymbolAddress(&pAgg, g_agg);
    cudaGetSymbolAddress(&pT, g_T);
    cudaGetSymbolAddress(&pNv, g_nv);
    cudaGetSymbolAddress(&pKk, g_kk);

    static bool inited = false;
    static cudaStream_t sB;
    static cudaEvent_t evFork, evJoin;
    if (!inited) {
        cudaStreamCreateWithFlags(&sB, cudaStreamNonBlocking);
        cudaEventCreateWithFlags(&evFork, cudaEventDisableTiming);
        cudaEventCreateWithFlags(&evJoin, cudaEventDisableTiming);
        cudaFuncSetAttribute(gemm_fp16<true, false, 1>,
                             cudaFuncAttributeMaxDynamicSharedMemorySize, GEMM_SMEM);
        cudaFuncSetAttribute(gemm_fp16<false, true, 2>,
                             cudaFuncAttributeMaxDynamicSharedMemorySize, GEMM_SMEM);
        inited = true;
    }

    prep_kernel<<<PREP_TOTAL, 256>>>(X, mask, W1, W2);

    cudaEventRecord(evFork, 0);
    cudaStreamWaitEvent(sB, evFork, 0);

    for (int h = 0; h < 2; h++) {
        cudaStream_t st = (h == 0) ? 0 : sB;
        const __half* Xh = (const __half*)pXh + (size_t)h * HB * N_ * DIN_;
        __half* H1h = (__half*)pH1 + (size_t)h * HB * N_ * DH_;
        __half* ETh = (__half*)pET + (size_t)h * HB * DH_ * N_;
        float* aggh = (float*)pAgg + (size_t)h * HB * DH_;
        float* Th = (float*)pT + (size_t)h * HB * DH_;
        const int* nvh = (const int*)pNv + h * HB;
        const int* kkh = (const int*)pKk + h * HB;
        float* outh = out + h * HB * 10;

        // GEMM1 half: H1[m,h'] = relu(X[m,:]·W1T[h',:] + b1[h'])
        gemm_fp16<true, false, 1><<<dim3(DH_ / BN, (HB * N_) / BM, 1), 256, GEMM_SMEM, st>>>(
            Xh, (const __half*)pW1T, b1, H1h, nvh, DIN_, DH_, 0, 0);

        // GEMM2 half (transposed out): ET[b][h'][n] = W2T[h',:]·H1[b][n,:] + b2[h']
        gemm_fp16<false, true, 2><<<dim3(N_ / BN, DH_ / BM, HB), 256, GEMM_SMEM, st>>>(
            (const __half*)pW2T, H1h, b2, ETh, nvh, DH_, N_,
            (size_t)N_ * DH_, (size_t)DH_ * N_);

        select_kernel<<<(HB * DH_) / 8, 256, 0, st>>>(ETh, aggh, nvh, kkh);
        decode1_kernel<<<dim3(8, HB / 4), 128, 0, st>>>(W3, b3, aggh, Th);
        decode2_kernel<<<(HB * 10 + 7) / 8, 256, 0, st>>>(W4, b4, Th, outh);
    }

    cudaEventRecord(evJoin, sB);
    cudaStreamWaitEvent(0, evJoin, 0);
}